// round 13
// baseline (speedup 1.0000x reference)
#include <cuda_runtime.h>
#include <math.h>
#include <stdint.h>

// B=32, T=128, I=512, H=512, L=2, O=512
__device__ float g_xh[4096 * 1024];   // input proj zr, row m=b*128+t
__device__ float g_xr[4096 * 512];    // input proj r-gate input
__device__ float g_out1[4096 * 512];  // layer-1 fwd outputs
__device__ float g_h[2 * 16384];      // h double buffer, [buf][b][j]
__device__ float g_hr1[32 * 512];     // reverse step1 hidden (b, j)
__device__ float g_hr2T[512 * 32];    // reverse step2 hidden (j, b)
__device__ unsigned g_flags[128 * 32]; // per-CTA barrier flag lines

#define FMA2(acc, a, b) \
    asm("fma.rn.f32x2 %0, %1, %2, %0;" : "+l"(acc) : "l"(a), "l"(b))
#define PACK2(dst, lo, hi) \
    asm("mov.b64 %0, {%1, %2};" : "=l"(dst) : "f"(lo), "f"(hi))
#define UNPACK2(lo, hi, src) \
    asm("mov.b64 {%0, %1}, %2;" : "=f"(lo), "=f"(hi) : "l"(src))
#define LDS_V2U64(a, b, addr) \
    asm("ld.shared.v2.u64 {%0, %1}, [%2];" : "=l"(a), "=l"(b) : "r"(addr))

__device__ __forceinline__ uint32_t su32(const void* p) {
    uint32_t a;
    asm("{ .reg .u64 t; cvta.to.shared.u64 t, %1; cvt.u32.u64 %0, t; }"
        : "=r"(a) : "l"(p));
    return a;
}
__device__ __forceinline__ unsigned ld_acq(const unsigned* p) {
    unsigned v;
    asm volatile("ld.acquire.gpu.u32 %0, [%1];" : "=r"(v) : "l"(p));
    return v;
}
__device__ __forceinline__ void st_rel(unsigned* p, unsigned v) {
    asm volatile("st.release.gpu.u32 [%0], %1;" :: "l"(p), "r"(v));
}

__global__ void init_kernel() {
    unsigned tid = blockIdx.x * blockDim.x + threadIdx.x;
    for (unsigned i = tid; i < 32768u; i += gridDim.x * blockDim.x) g_h[i] = 0.f;
    for (unsigned i = tid; i < 4096u; i += gridDim.x * blockDim.x) g_flags[i] = 0u;
}

__global__ void zero_h_kernel() {
    unsigned tid = blockIdx.x * blockDim.x + threadIdx.x;
    for (unsigned i = tid; i < 16384u; i += gridDim.x * blockDim.x) g_h[i] = 0.f;
}

// C(4096,N) = A(4096,512) @ W(512,N) + bias, f32x2-packed accumulators.
__global__ void __launch_bounds__(256) bulk_gemm(
    const float* __restrict__ Aext, int src_sel,
    const float* __restrict__ W, const float* __restrict__ bias,
    int N, int dst_sel)
{
    __shared__ __align__(16) float As[16][136];
    __shared__ __align__(16) float Bs[16][136];
    const float* A = src_sel ? g_out1 : Aext;
    float* dst = dst_sel ? g_xr : g_xh;

    unsigned long long accp[8][4];
#pragma unroll
    for (int i = 0; i < 8; i++)
#pragma unroll
        for (int j = 0; j < 4; j++) accp[i][j] = 0ULL;

    int tid = threadIdx.x, tx = tid & 15, ty = tid >> 4;
    int row0 = blockIdx.y * 128, col0 = blockIdx.x * 128;
    uint32_t bs_base = su32(&Bs[0][0]);

    for (int k0 = 0; k0 < 512; k0 += 16) {
#pragma unroll
        for (int i = 0; i < 2; i++) {
            int t = tid + i * 256;
            int r = t >> 2, kq = (t & 3) << 2;
            float4 v = *(const float4*)&A[(size_t)(row0 + r) * 512 + k0 + kq];
            As[kq + 0][r] = v.x; As[kq + 1][r] = v.y;
            As[kq + 2][r] = v.z; As[kq + 3][r] = v.w;
        }
#pragma unroll
        for (int i = 0; i < 2; i++) {
            int t = tid + i * 256;
            int kr = t >> 5, nq = (t & 31) << 2;
            *(float4*)&Bs[kr][nq] = *(const float4*)&W[(size_t)(k0 + kr) * N + col0 + nq];
        }
        __syncthreads();
#pragma unroll
        for (int kk = 0; kk < 16; kk++) {
            float a[8];
            *(float4*)&a[0] = *(float4*)&As[kk][ty * 8];
            *(float4*)&a[4] = *(float4*)&As[kk][ty * 8 + 4];
            unsigned long long b01, b23, b45, b67;
            uint32_t ba = bs_base + (uint32_t)(kk * 136 + tx * 8) * 4u;
            LDS_V2U64(b01, b23, ba);
            LDS_V2U64(b45, b67, ba + 16);
#pragma unroll
            for (int i = 0; i < 8; i++) {
                unsigned long long ap;
                PACK2(ap, a[i], a[i]);
                FMA2(accp[i][0], ap, b01);
                FMA2(accp[i][1], ap, b23);
                FMA2(accp[i][2], ap, b45);
                FMA2(accp[i][3], ap, b67);
            }
        }
        __syncthreads();
    }
#pragma unroll
    for (int i = 0; i < 8; i++) {
        int row = row0 + ty * 8 + i;
#pragma unroll
        for (int jp = 0; jp < 4; jp++) {
            float f0, f1;
            UNPACK2(f0, f1, accp[i][jp]);
            int col = col0 + tx * 8 + jp * 2;
            dst[(size_t)row * N + col]     = f0 + __ldg(&bias[col]);
            dst[(size_t)row * N + col + 1] = f1 + __ldg(&bias[col + 1]);
        }
    }
}

// Persistent forward GRU scan v5 (fixed byte-offset arithmetic).
// 128 CTAs = 4 groups x 32. Group g owns batches [g*8, g*8+8); CTA-in-group
// cg owns hidden cols [cg*16, cg*16+16). Weights (96KB) persist in SMEM.
// Dyn SMEM floats: sw 24576 | hs 4608 | red 3584 | sb 48
#define SCAN_SMEM_BYTES ((24576 + 4608 + 3584 + 48) * 4)

__global__ void __launch_bounds__(256) scan_kernel(
    int layer,
    const float* __restrict__ Whh, const float* __restrict__ bhh,
    const float* __restrict__ Whr, const float* __restrict__ bhr)
{
    extern __shared__ __align__(16) float sm[];
    float* sw = sm;            // [k][gate*16 + jl], 512*48
    float* hs = sw + 24576;    // [hj][b] stride 9, 512*9
    float* red = hs + 4608;    // [warp][lane*14 + 0..11]
    float* sb = red + 3584;    // [gate*16 + jl]

    const int tid = threadIdx.x;
    const int warp = tid >> 5, lane = tid & 31;
    const int grp = blockIdx.x >> 5;      // batch group
    const int cg = blockIdx.x & 31;       // cta in group
    const int b0 = grp * 8;
    const int j0 = cg * 16;
    const unsigned step_base = (unsigned)layer * 128u;

    // persistent weights: sw[k*48 + gate*16 + jl], global j = j0 + jl
    for (int i = tid; i < 512 * 48; i += 256) {
        int k = i / 48, rem = i - k * 48;
        int gate = rem >> 4, jl = rem & 15;
        float v;
        if (gate == 0)      v = Whh[k * 1024 + j0 + jl];
        else if (gate == 1) v = Whh[k * 1024 + 512 + j0 + jl];
        else                v = Whr[k * 512 + j0 + jl];
        sw[i] = v;
    }
    if (tid < 48) {
        int gate = tid >> 4, jl = tid & 15;
        sb[tid] = (gate == 0) ? bhh[j0 + jl]
                : (gate == 1) ? bhh[512 + j0 + jl]
                              : bhr[j0 + jl];
    }
    __syncthreads();

    const float* xh = g_xh;
    const float* xr = g_xr;
    float* out = g_out1;

    // compute identity: warp = 64-k chunk; lane = jq(4) x bc(8)
    const int jq = lane >> 3, bc = lane & 7;
    const int k0 = warp * 64;
    const uint32_t swb = su32(sw) + (uint32_t)(k0 * 48 + jq * 4) * 4u;  // bytes
    const uint32_t hsb = su32(hs) + (uint32_t)(k0 * 9 + bc) * 4u;      // bytes

    // gating identity (tid < 128): jloc in [0,16), b2 in [0,8)
    const int jloc = tid >> 3, b2 = tid & 7;

    unsigned* myflag = &g_flags[blockIdx.x * 32];
    const unsigned* pollflag = &g_flags[(grp * 32 + (tid & 31)) * 32];

    for (int t = 0; t < 128; t++) {
        const float* hcur = g_h + (t & 1) * 16384;
        float* hnxt = g_h + ((t + 1) & 1) * 16384;

        // prefetch gating inputs (independent of h)
        float pz = 0.f, pr = 0.f, pg = 0.f;
        if (tid < 128) {
            int m = (b0 + b2) * 128 + t;
            int jg = j0 + jloc;
            pz = __ldg(&xh[(size_t)m * 1024 + jg]);
            pr = __ldg(&xh[(size_t)m * 1024 + 512 + jg]);
            pg = __ldg(&xr[(size_t)m * 512 + jg]);
        }

        // stage group h (8 batches x 512) into hs[hj*9 + b], bypass L1
        for (int u = tid; u < 1024; u += 256) {
            int bl = u >> 7, j4 = (u & 127) << 2;
            float4 v = __ldcg((const float4*)&hcur[(b0 + bl) * 512 + j4]);
            hs[(j4 + 0) * 9 + bl] = v.x;
            hs[(j4 + 1) * 9 + bl] = v.y;
            hs[(j4 + 2) * 9 + bl] = v.z;
            hs[(j4 + 3) * 9 + bl] = v.w;
        }
        __syncthreads();

        unsigned long long az01 = 0, az23 = 0, ar01 = 0, ar23 = 0;
        unsigned long long ag01 = 0, ag23 = 0;
#pragma unroll
        for (int k = 0; k < 64; k++) {
            float hv;
            asm("ld.shared.f32 %0, [%1];" : "=f"(hv)
                : "r"(hsb + (uint32_t)(k * 36)));        // 9 floats = 36 B/row
            unsigned long long hh;
            PACK2(hh, hv, hv);
            unsigned long long wz01, wz23, wr01, wr23, wg01, wg23;
            uint32_t a = swb + (uint32_t)(k * 192);      // 48 floats = 192 B/row
            LDS_V2U64(wz01, wz23, a);
            LDS_V2U64(wr01, wr23, a + 64);
            LDS_V2U64(wg01, wg23, a + 128);
            FMA2(az01, wz01, hh); FMA2(az23, wz23, hh);
            FMA2(ar01, wr01, hh); FMA2(ar23, wr23, hh);
            FMA2(ag01, wg01, hh); FMA2(ag23, wg23, hh);
        }
        {
            unsigned long long* rp =
                (unsigned long long*)&red[warp * 448 + lane * 14];
            rp[0] = az01; rp[1] = az23;
            rp[2] = ar01; rp[3] = ar23;
            rp[4] = ag01; rp[5] = ag23;
        }
        __syncthreads();

        if (tid < 128) {
            int rl = (jloc >> 2) * 8 + b2;   // source lane
            int jl4 = jloc & 3;
            float z = 0.f, r = 0.f, g = 0.f;
#pragma unroll
            for (int s = 0; s < 8; s++) {
                const float* q = &red[s * 448 + rl * 14];
                z += q[jl4];
                r += q[4 + jl4];
                g += q[8 + jl4];
            }
            int jg = j0 + jloc, bg = b0 + b2;
            z += pz + sb[jloc];
            r += pr + sb[16 + jloc];
            float zs = 1.f / (1.f + __expf(-z));
            float rs = 1.f / (1.f + __expf(-r));
            float gg = tanhf((g + sb[32 + jloc]) * rs + pg);
            float hold = hs[jg * 9 + b2];
            float hnew = zs * hold + (1.f - zs) * gg;
            hnxt[bg * 512 + jg] = hnew;
            if (!layer) out[(size_t)(bg * 128 + t) * 512 + jg] = hnew;
        }

        // group-local flag barrier (32 CTAs)
        unsigned target = step_base + (unsigned)(t + 1);
        __syncthreads();
        if (tid == 0) st_rel(myflag, target);
        if (tid < 32) {
            while (ld_acq(pollflag) < target) { }
        }
        __syncthreads();
    }
}

// One GRU step with h=0 (reverse branch collapses to two of these).
__global__ void __launch_bounds__(512) rev_step(
    const float* __restrict__ Xext, int ldx, int src_sel,
    const float* __restrict__ Wxh, const float* __restrict__ bxh,
    const float* __restrict__ bhh,
    const float* __restrict__ Wxr, const float* __restrict__ bxr,
    const float* __restrict__ bhr, int dst_trans)
{
    __shared__ float xs[256 * 33];
    const float* X = src_sel ? g_hr1 : Xext;
    int tid = threadIdx.x;
    int jl = tid >> 5, b = tid & 31;
    int j = blockIdx.x * 16 + jl;
    float az = 0.f, ar = 0.f, ag = 0.f;

    for (int k0 = 0; k0 < 512; k0 += 256) {
        __syncthreads();
        int half = tid >> 8, kl = tid & 255;
        for (int b2 = half; b2 < 32; b2 += 2)
            xs[kl * 33 + b2] = X[(size_t)b2 * ldx + k0 + kl];
        __syncthreads();
#pragma unroll 8
        for (int k = 0; k < 256; k++) {
            float xv = xs[k * 33 + b];
            int kk = k0 + k;
            az += xv * __ldg(&Wxh[(size_t)kk * 1024 + j]);
            ar += xv * __ldg(&Wxh[(size_t)kk * 1024 + 512 + j]);
            ag += xv * __ldg(&Wxr[(size_t)kk * 512 + j]);
        }
    }
    float z = 1.f / (1.f + __expf(-(az + __ldg(&bxh[j]) + __ldg(&bhh[j]))));
    float r = 1.f / (1.f + __expf(-(ar + __ldg(&bxh[512 + j]) + __ldg(&bhh[512 + j]))));
    float g = tanhf(__ldg(&bhr[j]) * r + ag + __ldg(&bxr[j]));
    float h = (1.f - z) * g;
    if (dst_trans) g_hr2T[j * 32 + b] = h;
    else           g_hr1[b * 512 + j] = h;
}

// out(32,512) = [h_fwd_final | hr2](32,1024) @ Wfc + bfc
// h_fwd_final in g_h buf0, layout [b][j]; hr2 in g_hr2T [j][b].
__global__ void __launch_bounds__(512) fc_kernel(
    const float* __restrict__ Wfc, const float* __restrict__ bfc,
    float* __restrict__ out)
{
    int tid = threadIdx.x;
    int jl = tid >> 5, b = tid & 31;
    int j = blockIdx.x * 16 + jl;
    float acc = 0.f;
#pragma unroll 4
    for (int k = 0; k < 512; k++)
        acc += g_h[b * 512 + k] * __ldg(&Wfc[(size_t)k * 512 + j]);
#pragma unroll 4
    for (int k = 0; k < 512; k++)
        acc += g_hr2T[k * 32 + b] * __ldg(&Wfc[(size_t)(512 + k) * 512 + j]);
    out[b * 512 + j] = acc + __ldg(&bfc[j]);
}

extern "C" void kernel_launch(void* const* d_in, const int* in_sizes, int n_in,
                              void* d_out, int out_size) {
    const float* x   = (const float*)d_in[0];
    const float* Wxh = (const float*)d_in[1];
    const float* bxh = (const float*)d_in[2];
    const float* Whh = (const float*)d_in[3];
    const float* bhh = (const float*)d_in[4];
    const float* Wxr = (const float*)d_in[5];
    const float* bxr = (const float*)d_in[6];
    const float* Whr = (const float*)d_in[7];
    const float* bhr = (const float*)d_in[8];
    const float* Wfc = (const float*)d_in[9];
    const float* bfc = (const float*)d_in[10];
    float* out = (float*)d_out;

    cudaFuncSetAttribute(scan_kernel,
        cudaFuncAttributeMaxDynamicSharedMemorySize, SCAN_SMEM_BYTES);

    const size_t WH = 512 * 1024, WR = 512 * 512;

    init_kernel<<<64, 256>>>();

    dim3 g1(8, 32), g2(4, 32);
    // layer 0 forward (slab 0)
    bulk_gemm<<<g1, 256>>>(x, 0, Wxh, bxh, 1024, 0);
    bulk_gemm<<<g2, 256>>>(x, 0, Wxr, bxr, 512, 1);
    scan_kernel<<<128, 256, SCAN_SMEM_BYTES>>>(0, Whh, bhh, Whr, bhr);

    // layer 1 forward (slab 2)
    zero_h_kernel<<<16, 256>>>();
    bulk_gemm<<<g1, 256>>>(nullptr, 1, Wxh + 2 * WH, bxh + 2 * 1024, 1024, 0);
    bulk_gemm<<<g2, 256>>>(nullptr, 1, Wxr + 2 * WR, bxr + 2 * 512, 512, 1);
    scan_kernel<<<128, 256, SCAN_SMEM_BYTES>>>(1,
        Whh + 2 * WH, bhh + 2 * 1024, Whr + 2 * WR, bhr + 2 * 512);

    // reverse branch: two single steps (slabs 1, 3)
    rev_step<<<32, 512>>>(x + 127 * 512, 128 * 512, 0,
        Wxh + 1 * WH, bxh + 1 * 1024, bhh + 1 * 1024,
        Wxr + 1 * WR, bxr + 1 * 512, bhr + 1 * 512, 0);
    rev_step<<<32, 512>>>(nullptr, 512, 1,
        Wxh + 3 * WH, bxh + 3 * 1024, bhh + 3 * 1024,
        Wxr + 3 * WR, bxr + 3 * 512, bhr + 3 * 512, 1);

    fc_kernel<<<32, 512>>>(Wfc, bfc, out);
}

// round 14
// speedup vs baseline: 1.1347x; 1.1347x over previous
#include <cuda_runtime.h>
#include <math.h>
#include <stdint.h>

// B=32, T=128, I=512, H=512, L=2, O=512
__device__ float g_xh[4096 * 1024];   // layer-1 input proj zr, row m=b*128+t
__device__ float g_xr[4096 * 512];    // layer-1 input proj g-input
__device__ float g_h1[129 * 16384];   // h1 history, slab t+1 = h1[t], [j][b]
__device__ float g_h2[129 * 16384];   // h2 history
__device__ float g_hr1[32 * 512];     // reverse step1 hidden (b, j)
__device__ float g_hr2T[512 * 32];    // reverse step2 hidden (j, b)
__device__ unsigned g_flags[128 * 32]; // per-CTA progress flags (own line)

#define FMA2(acc, a, b) \
    asm("fma.rn.f32x2 %0, %1, %2, %0;" : "+l"(acc) : "l"(a), "l"(b))
#define PACK2(dst, lo, hi) \
    asm("mov.b64 %0, {%1, %2};" : "=l"(dst) : "f"(lo), "f"(hi))
#define UNPACK2(lo, hi, src) \
    asm("mov.b64 {%0, %1}, %2;" : "=f"(lo), "=f"(hi) : "l"(src))
#define LDS_V2U64(a, b, addr) \
    asm("ld.shared.v2.u64 {%0, %1}, [%2];" : "=l"(a), "=l"(b) : "r"(addr))

__device__ __forceinline__ uint32_t su32(const void* p) {
    uint32_t a;
    asm("{ .reg .u64 t; cvta.to.shared.u64 t, %1; cvt.u32.u64 %0, t; }"
        : "=r"(a) : "l"(p));
    return a;
}
__device__ __forceinline__ unsigned ld_acq(const unsigned* p) {
    unsigned v;
    asm volatile("ld.acquire.gpu.u32 %0, [%1];" : "=r"(v) : "l"(p));
    return v;
}
__device__ __forceinline__ void st_rel(unsigned* p, unsigned v) {
    asm volatile("st.release.gpu.u32 [%0], %1;" :: "l"(p), "r"(v));
}

__global__ void init_kernel() {
    unsigned tid = blockIdx.x * blockDim.x + threadIdx.x;
    unsigned n = gridDim.x * blockDim.x;
    for (unsigned i = tid; i < 16384u; i += n) { g_h1[i] = 0.f; g_h2[i] = 0.f; }
    for (unsigned i = tid; i < 4096u; i += n) g_flags[i] = 0u;
}

// C(4096,N) = A(4096,512) @ W(512,N) + bias, f32x2-packed accumulators.
__global__ void __launch_bounds__(256) bulk_gemm(
    const float* __restrict__ A,
    const float* __restrict__ W, const float* __restrict__ bias,
    int N, int dst_sel)
{
    __shared__ __align__(16) float As[16][136];
    __shared__ __align__(16) float Bs[16][136];
    float* dst = dst_sel ? g_xr : g_xh;

    unsigned long long accp[8][4];
#pragma unroll
    for (int i = 0; i < 8; i++)
#pragma unroll
        for (int j = 0; j < 4; j++) accp[i][j] = 0ULL;

    int tid = threadIdx.x, tx = tid & 15, ty = tid >> 4;
    int row0 = blockIdx.y * 128, col0 = blockIdx.x * 128;
    uint32_t bs_base = su32(&Bs[0][0]);

    for (int k0 = 0; k0 < 512; k0 += 16) {
#pragma unroll
        for (int i = 0; i < 2; i++) {
            int t = tid + i * 256;
            int r = t >> 2, kq = (t & 3) << 2;
            float4 v = *(const float4*)&A[(size_t)(row0 + r) * 512 + k0 + kq];
            As[kq + 0][r] = v.x; As[kq + 1][r] = v.y;
            As[kq + 2][r] = v.z; As[kq + 3][r] = v.w;
        }
#pragma unroll
        for (int i = 0; i < 2; i++) {
            int t = tid + i * 256;
            int kr = t >> 5, nq = (t & 31) << 2;
            *(float4*)&Bs[kr][nq] = *(const float4*)&W[(size_t)(k0 + kr) * N + col0 + nq];
        }
        __syncthreads();
#pragma unroll
        for (int kk = 0; kk < 16; kk++) {
            float a[8];
            *(float4*)&a[0] = *(float4*)&As[kk][ty * 8];
            *(float4*)&a[4] = *(float4*)&As[kk][ty * 8 + 4];
            unsigned long long b01, b23, b45, b67;
            uint32_t ba = bs_base + (uint32_t)(kk * 136 + tx * 8) * 4u;
            LDS_V2U64(b01, b23, ba);
            LDS_V2U64(b45, b67, ba + 16);
#pragma unroll
            for (int i = 0; i < 8; i++) {
                unsigned long long ap;
                PACK2(ap, a[i], a[i]);
                FMA2(accp[i][0], ap, b01);
                FMA2(accp[i][1], ap, b23);
                FMA2(accp[i][2], ap, b45);
                FMA2(accp[i][3], ap, b67);
            }
        }
        __syncthreads();
    }
#pragma unroll
    for (int i = 0; i < 8; i++) {
        int row = row0 + ty * 8 + i;
#pragma unroll
        for (int jp = 0; jp < 4; jp++) {
            float f0, f1;
            UNPACK2(f0, f1, accp[i][jp]);
            int col = col0 + tx * 8 + jp * 2;
            dst[(size_t)row * N + col]     = f0 + __ldg(&bias[col]);
            dst[(size_t)row * N + col + 1] = f1 + __ldg(&bias[col + 1]);
        }
    }
}

// Fused two-layer wavefront GRU scan.
// 128 CTAs x 512 threads (1/SM). CTAs 0-63: layer 1 (j-slice 8, reads h1[t],
// precomputed g_xh/g_xr). CTAs 64-127: layer 2 (j-slice 8, reads h2[t] AND
// h1[t] — input projection computed on the fly from SMEM weights).
// Histories are t-indexed (no overwrite); per-CTA monotonic flags = dataflow.
// SMEM floats: sw 24576 (L2; L1 uses 12288) | red 9216 | sb 32
#define FSCAN_SMEM_BYTES ((24576 + 9216 + 32) * 4)

__global__ void __launch_bounds__(512, 1) fused_scan(
    const float* __restrict__ Whh1, const float* __restrict__ bhh1,
    const float* __restrict__ Whr1, const float* __restrict__ bhr1,
    const float* __restrict__ Whh2, const float* __restrict__ bhh2,
    const float* __restrict__ Whr2, const float* __restrict__ bhr2,
    const float* __restrict__ Wxh2, const float* __restrict__ bxh2,
    const float* __restrict__ Wxr2, const float* __restrict__ bxr2)
{
    extern __shared__ __align__(16) float sm[];
    float* sw = sm;            // weights
    float* red = sm + 24576;   // partials: (warp*32+lane)*18
    float* sb = red + 9216;    // biases

    const int tid = threadIdx.x;
    const int warp = tid >> 5, lane = tid & 31;
    const bool isL2 = blockIdx.x >= 64;
    const int c = isL2 ? (int)blockIdx.x - 64 : (int)blockIdx.x;
    const int j0 = c * 8;

    if (!isL2) {
        // sw1[k*24 + gate*8 + jl]; gates z,r,G
        for (int i = tid; i < 12288; i += 512) {
            int k = i / 24, rem = i - k * 24;
            int g = rem >> 3, jl = rem & 7;
            float v = (g == 0) ? Whh1[k * 1024 + j0 + jl]
                    : (g == 1) ? Whh1[k * 1024 + 512 + j0 + jl]
                               : Whr1[k * 512 + j0 + jl];
            sw[i] = v;
        }
        if (tid < 24) {
            int g = tid >> 3, jl = tid & 7;
            sb[tid] = (g == 0) ? bhh1[j0 + jl]
                    : (g == 1) ? bhh1[512 + j0 + jl]
                               : bhr1[j0 + jl];
        }
    } else {
        // sw2[k*48 + grp*8 + jl]; grps: Whh_z, Whh_r, Whr(A), Wxh_z, Wxh_r, Wxr(X)
        for (int i = tid; i < 24576; i += 512) {
            int k = i / 48, rem = i - k * 48;
            int g = rem >> 3, jl = rem & 7;
            float v;
            if (g == 0)      v = Whh2[k * 1024 + j0 + jl];
            else if (g == 1) v = Whh2[k * 1024 + 512 + j0 + jl];
            else if (g == 2) v = Whr2[k * 512 + j0 + jl];
            else if (g == 3) v = Wxh2[k * 1024 + j0 + jl];
            else if (g == 4) v = Wxh2[k * 1024 + 512 + j0 + jl];
            else             v = Wxr2[k * 512 + j0 + jl];
            sw[i] = v;
        }
        if (tid < 32) {
            int g = tid >> 3, jl = tid & 7;
            sb[tid] = (g == 0) ? bxh2[j0 + jl] + bhh2[j0 + jl]
                    : (g == 1) ? bxh2[512 + j0 + jl] + bhh2[512 + j0 + jl]
                    : (g == 2) ? bhr2[j0 + jl]
                               : bxr2[j0 + jl];
        }
    }
    __syncthreads();

    // compute identity: warp = jh(2) x kc(8); lane = batch
    const int jh = warp >> 3, kc = warp & 7, k0 = kc * 64;
    const uint32_t swb = su32(sw) +
        (uint32_t)(isL2 ? (k0 * 192 + jh * 16) : (k0 * 96 + jh * 16));
    // gating identity (tid < 256): jloc = warp (0..7), b = lane
    const int jloc = warp & 7;
    unsigned* myflag = &g_flags[blockIdx.x * 32];

    for (int t = 0; t < 128; t++) {
        // dataflow waits (producer flags only; histories never overwritten)
        if (!isL2) {
            if (tid < 64)
                while (ld_acq(&g_flags[tid * 32]) < (unsigned)t) { }
        } else {
            if (tid < 64) {
                unsigned tg = (unsigned)(t + 1);
                while (ld_acq(&g_flags[tid * 32]) < tg) { }
            } else if (tid < 128) {
                while (ld_acq(&g_flags[tid * 32]) < (unsigned)t) { }
            }
        }
        __syncthreads();

        // prefetch gating inputs
        float pz = 0.f, pr = 0.f, pg = 0.f, hold = 0.f;
        if (tid < 256) {
            int jg = j0 + jloc;
            if (!isL2) {
                int m = lane * 128 + t;
                pz = __ldg(&g_xh[(size_t)m * 1024 + jg]);
                pr = __ldg(&g_xh[(size_t)m * 1024 + 512 + jg]);
                pg = __ldg(&g_xr[(size_t)m * 512 + jg]);
                hold = __ldcg(&g_h1[(size_t)t * 16384 + jg * 32 + lane]);
            } else {
                hold = __ldcg(&g_h2[(size_t)t * 16384 + jg * 32 + lane]);
            }
        }

        if (!isL2) {
            const float* hb = g_h1 + (size_t)t * 16384;
            unsigned long long az01 = 0, az23 = 0, ar01 = 0, ar23 = 0;
            unsigned long long aA01 = 0, aA23 = 0;
#pragma unroll
            for (int k = 0; k < 64; k++) {
                float hv = __ldcg(&hb[(k0 + k) * 32 + lane]);
                unsigned long long hh;
                PACK2(hh, hv, hv);
                unsigned long long wz01, wz23, wr01, wr23, wg01, wg23;
                uint32_t a = swb + (uint32_t)(k * 96);
                LDS_V2U64(wz01, wz23, a);
                LDS_V2U64(wr01, wr23, a + 32);
                LDS_V2U64(wg01, wg23, a + 64);
                FMA2(az01, wz01, hh); FMA2(az23, wz23, hh);
                FMA2(ar01, wr01, hh); FMA2(ar23, wr23, hh);
                FMA2(aA01, wg01, hh); FMA2(aA23, wg23, hh);
            }
            unsigned long long* rp =
                (unsigned long long*)&red[(warp * 32 + lane) * 18];
            rp[0] = az01; rp[1] = az23;
            rp[2] = ar01; rp[3] = ar23;
            rp[4] = aA01; rp[5] = aA23;
        } else {
            const float* hb2 = g_h2 + (size_t)t * 16384;
            const float* hb1 = g_h1 + (size_t)(t + 1) * 16384;
            unsigned long long az01 = 0, az23 = 0, ar01 = 0, ar23 = 0;
            unsigned long long aA01 = 0, aA23 = 0, aX01 = 0, aX23 = 0;
#pragma unroll 32
            for (int k = 0; k < 64; k++) {
                float h2v = __ldcg(&hb2[(k0 + k) * 32 + lane]);
                float h1v = __ldcg(&hb1[(k0 + k) * 32 + lane]);
                unsigned long long h2p, h1p;
                PACK2(h2p, h2v, h2v);
                PACK2(h1p, h1v, h1v);
                uint32_t a = swb + (uint32_t)(k * 192);
                unsigned long long w01, w23;
                LDS_V2U64(w01, w23, a);        // Whh_z
                FMA2(az01, w01, h2p); FMA2(az23, w23, h2p);
                LDS_V2U64(w01, w23, a + 32);   // Whh_r
                FMA2(ar01, w01, h2p); FMA2(ar23, w23, h2p);
                LDS_V2U64(w01, w23, a + 64);   // Whr (A)
                FMA2(aA01, w01, h2p); FMA2(aA23, w23, h2p);
                LDS_V2U64(w01, w23, a + 96);   // Wxh_z
                FMA2(az01, w01, h1p); FMA2(az23, w23, h1p);
                LDS_V2U64(w01, w23, a + 128);  // Wxh_r
                FMA2(ar01, w01, h1p); FMA2(ar23, w23, h1p);
                LDS_V2U64(w01, w23, a + 160);  // Wxr (X)
                FMA2(aX01, w01, h1p); FMA2(aX23, w23, h1p);
            }
            unsigned long long* rp =
                (unsigned long long*)&red[(warp * 32 + lane) * 18];
            rp[0] = az01; rp[1] = az23;
            rp[2] = ar01; rp[3] = ar23;
            rp[4] = aA01; rp[5] = aA23;
            rp[6] = aX01; rp[7] = aX23;
        }
        __syncthreads();

        if (tid < 256) {
            int jh2 = jloc >> 2, q = jloc & 3;
            float z = 0.f, r = 0.f, A = 0.f, X = 0.f;
#pragma unroll
            for (int kc2 = 0; kc2 < 8; kc2++) {
                const float* qp = &red[((jh2 * 8 + kc2) * 32 + lane) * 18];
                z += qp[q];
                r += qp[4 + q];
                A += qp[8 + q];
                if (isL2) X += qp[12 + q];
            }
            int jg = j0 + jloc;
            float zs, rs, gg, hnew;
            if (!isL2) {
                z += pz + sb[jloc];
                r += pr + sb[8 + jloc];
                zs = 1.f / (1.f + __expf(-z));
                rs = 1.f / (1.f + __expf(-r));
                gg = tanhf((A + sb[16 + jloc]) * rs + pg);
                hnew = zs * hold + (1.f - zs) * gg;
                __stcg(&g_h1[(size_t)(t + 1) * 16384 + jg * 32 + lane], hnew);
            } else {
                z += sb[jloc];
                r += sb[8 + jloc];
                A += sb[16 + jloc];
                X += sb[24 + jloc];
                zs = 1.f / (1.f + __expf(-z));
                rs = 1.f / (1.f + __expf(-r));
                gg = tanhf(A * rs + X);
                hnew = zs * hold + (1.f - zs) * gg;
                __stcg(&g_h2[(size_t)(t + 1) * 16384 + jg * 32 + lane], hnew);
            }
        }
        __syncthreads();
        if (tid == 0) st_rel(myflag, (unsigned)(t + 1));
    }
}

// One GRU step with h=0 (reverse branch collapses to two of these).
__global__ void __launch_bounds__(512) rev_step(
    const float* __restrict__ Xext, int ldx, int src_sel,
    const float* __restrict__ Wxh, const float* __restrict__ bxh,
    const float* __restrict__ bhh,
    const float* __restrict__ Wxr, const float* __restrict__ bxr,
    const float* __restrict__ bhr, int dst_trans)
{
    __shared__ float xs[256 * 33];
    const float* X = src_sel ? g_hr1 : Xext;
    int tid = threadIdx.x;
    int jl = tid >> 5, b = tid & 31;
    int j = blockIdx.x * 16 + jl;
    float az = 0.f, ar = 0.f, ag = 0.f;

    for (int k0 = 0; k0 < 512; k0 += 256) {
        __syncthreads();
        int half = tid >> 8, kl = tid & 255;
        for (int b2 = half; b2 < 32; b2 += 2)
            xs[kl * 33 + b2] = X[(size_t)b2 * ldx + k0 + kl];
        __syncthreads();
#pragma unroll 8
        for (int k = 0; k < 256; k++) {
            float xv = xs[k * 33 + b];
            int kk = k0 + k;
            az += xv * __ldg(&Wxh[(size_t)kk * 1024 + j]);
            ar += xv * __ldg(&Wxh[(size_t)kk * 1024 + 512 + j]);
            ag += xv * __ldg(&Wxr[(size_t)kk * 512 + j]);
        }
    }
    float z = 1.f / (1.f + __expf(-(az + __ldg(&bxh[j]) + __ldg(&bhh[j]))));
    float r = 1.f / (1.f + __expf(-(ar + __ldg(&bxh[512 + j]) + __ldg(&bhh[512 + j]))));
    float g = tanhf(__ldg(&bhr[j]) * r + ag + __ldg(&bxr[j]));
    float h = (1.f - z) * g;
    if (dst_trans) g_hr2T[j * 32 + b] = h;
    else           g_hr1[b * 512 + j] = h;
}

// out(32,512) = [h2_final | hr2](32,1024) @ Wfc + bfc
// h2_final = g_h2 slab 128 ([j][b]); hr2 in g_hr2T ([j][b]).
__global__ void __launch_bounds__(512) fc_kernel(
    const float* __restrict__ Wfc, const float* __restrict__ bfc,
    float* __restrict__ out)
{
    int tid = threadIdx.x;
    int jl = tid >> 5, b = tid & 31;
    int j = blockIdx.x * 16 + jl;
    const float* h2f = g_h2 + (size_t)128 * 16384;
    float acc = 0.f;
#pragma unroll 4
    for (int k = 0; k < 512; k++)
        acc += h2f[k * 32 + b] * __ldg(&Wfc[(size_t)k * 512 + j]);
#pragma unroll 4
    for (int k = 0; k < 512; k++)
        acc += g_hr2T[k * 32 + b] * __ldg(&Wfc[(size_t)(512 + k) * 512 + j]);
    out[b * 512 + j] = acc + __ldg(&bfc[j]);
}

extern "C" void kernel_launch(void* const* d_in, const int* in_sizes, int n_in,
                              void* d_out, int out_size) {
    const float* x   = (const float*)d_in[0];
    const float* Wxh = (const float*)d_in[1];
    const float* bxh = (const float*)d_in[2];
    const float* Whh = (const float*)d_in[3];
    const float* bhh = (const float*)d_in[4];
    const float* Wxr = (const float*)d_in[5];
    const float* bxr = (const float*)d_in[6];
    const float* Whr = (const float*)d_in[7];
    const float* bhr = (const float*)d_in[8];
    const float* Wfc = (const float*)d_in[9];
    const float* bfc = (const float*)d_in[10];
    float* out = (float*)d_out;

    cudaFuncSetAttribute(fused_scan,
        cudaFuncAttributeMaxDynamicSharedMemorySize, FSCAN_SMEM_BYTES);

    const size_t WH = 512 * 1024, WR = 512 * 512;

    init_kernel<<<64, 256>>>();

    // layer-1 input projections (slab 0)
    dim3 g1(8, 32), g2(4, 32);
    bulk_gemm<<<g1, 256>>>(x, Wxh, bxh, 1024, 0);
    bulk_gemm<<<g2, 256>>>(x, Wxr, bxr, 512, 1);

    // fused two-layer wavefront scan (layer-1 slab 0, layer-2 slab 2)
    fused_scan<<<128, 512, FSCAN_SMEM_BYTES>>>(
        Whh, bhh, Whr, bhr,
        Whh + 2 * WH, bhh + 2 * 1024, Whr + 2 * WR, bhr + 2 * 512,
        Wxh + 2 * WH, bxh + 2 * 1024, Wxr + 2 * WR, bxr + 2 * 512);

    // reverse branch: two single steps (slabs 1, 3)
    rev_step<<<32, 512>>>(x + 127 * 512, 128 * 512, 0,
        Wxh + 1 * WH, bxh + 1 * 1024, bhh + 1 * 1024,
        Wxr + 1 * WR, bxr + 1 * 512, bhr + 1 * 512, 0);
    rev_step<<<32, 512>>>(nullptr, 512, 1,
        Wxh + 3 * WH, bxh + 3 * 1024, bhh + 3 * 1024,
        Wxr + 3 * WR, bxr + 3 * 512, bhr + 3 * 512, 1);

    fc_kernel<<<32, 512>>>(Wfc, bfc, out);
}

// round 15
// speedup vs baseline: 1.2293x; 1.0833x over previous
#include <cuda_runtime.h>
#include <math.h>
#include <stdint.h>

// B=32, T=128, I=512, H=512, L=2, O=512
__device__ float g_xh[4096 * 1024];   // layer-1 input proj zr, row m=b*128+t
__device__ float g_xr[4096 * 512];    // layer-1 input proj g-input
__device__ float g_h1[129 * 16384];   // h1 history, slab t+1 = h1 after step t
__device__ float g_h2[129 * 16384];   // h2 history, layout [j][b] per slab
__device__ float g_hr1[32 * 512];     // reverse step1 hidden (b, j)
__device__ float g_hr2T[512 * 32];    // reverse step2 hidden (j, b)
__device__ unsigned g_flags[128 * 32]; // per-CTA progress flags (own line)

#define FMA2(acc, a, b) \
    asm("fma.rn.f32x2 %0, %1, %2, %0;" : "+l"(acc) : "l"(a), "l"(b))
#define PACK2(dst, lo, hi) \
    asm("mov.b64 %0, {%1, %2};" : "=l"(dst) : "f"(lo), "f"(hi))
#define UNPACK2(lo, hi, src) \
    asm("mov.b64 {%0, %1}, %2;" : "=f"(lo), "=f"(hi) : "l"(src))
#define LDS_V2U64(a, b, addr) \
    asm("ld.shared.v2.u64 {%0, %1}, [%2];" : "=l"(a), "=l"(b) : "r"(addr))

__device__ __forceinline__ uint32_t su32(const void* p) {
    uint32_t a;
    asm("{ .reg .u64 t; cvta.to.shared.u64 t, %1; cvt.u32.u64 %0, t; }"
        : "=r"(a) : "l"(p));
    return a;
}
__device__ __forceinline__ unsigned ld_acq(const unsigned* p) {
    unsigned v;
    asm volatile("ld.acquire.gpu.u32 %0, [%1];" : "=r"(v) : "l"(p));
    return v;
}
__device__ __forceinline__ void st_rel(unsigned* p, unsigned v) {
    asm volatile("st.release.gpu.u32 [%0], %1;" :: "l"(p), "r"(v));
}

__global__ void init_kernel() {
    unsigned tid = blockIdx.x * blockDim.x + threadIdx.x;
    unsigned n = gridDim.x * blockDim.x;
    for (unsigned i = tid; i < 16384u; i += n) { g_h1[i] = 0.f; g_h2[i] = 0.f; }
    for (unsigned i = tid; i < 4096u; i += n) g_flags[i] = 0u;
}

// C(4096,N) = A(4096,512) @ W(512,N) + bias, f32x2-packed accumulators.
__global__ void __launch_bounds__(256) bulk_gemm(
    const float* __restrict__ A,
    const float* __restrict__ W, const float* __restrict__ bias,
    int N, int dst_sel)
{
    __shared__ __align__(16) float As[16][136];
    __shared__ __align__(16) float Bs[16][136];
    float* dst = dst_sel ? g_xr : g_xh;

    unsigned long long accp[8][4];
#pragma unroll
    for (int i = 0; i < 8; i++)
#pragma unroll
        for (int j = 0; j < 4; j++) accp[i][j] = 0ULL;

    int tid = threadIdx.x, tx = tid & 15, ty = tid >> 4;
    int row0 = blockIdx.y * 128, col0 = blockIdx.x * 128;
    uint32_t bs_base = su32(&Bs[0][0]);

    for (int k0 = 0; k0 < 512; k0 += 16) {
#pragma unroll
        for (int i = 0; i < 2; i++) {
            int t = tid + i * 256;
            int r = t >> 2, kq = (t & 3) << 2;
            float4 v = *(const float4*)&A[(size_t)(row0 + r) * 512 + k0 + kq];
            As[kq + 0][r] = v.x; As[kq + 1][r] = v.y;
            As[kq + 2][r] = v.z; As[kq + 3][r] = v.w;
        }
#pragma unroll
        for (int i = 0; i < 2; i++) {
            int t = tid + i * 256;
            int kr = t >> 5, nq = (t & 31) << 2;
            *(float4*)&Bs[kr][nq] = *(const float4*)&W[(size_t)(k0 + kr) * N + col0 + nq];
        }
        __syncthreads();
#pragma unroll
        for (int kk = 0; kk < 16; kk++) {
            float a[8];
            *(float4*)&a[0] = *(float4*)&As[kk][ty * 8];
            *(float4*)&a[4] = *(float4*)&As[kk][ty * 8 + 4];
            unsigned long long b01, b23, b45, b67;
            uint32_t ba = bs_base + (uint32_t)(kk * 136 + tx * 8) * 4u;
            LDS_V2U64(b01, b23, ba);
            LDS_V2U64(b45, b67, ba + 16);
#pragma unroll
            for (int i = 0; i < 8; i++) {
                unsigned long long ap;
                PACK2(ap, a[i], a[i]);
                FMA2(accp[i][0], ap, b01);
                FMA2(accp[i][1], ap, b23);
                FMA2(accp[i][2], ap, b45);
                FMA2(accp[i][3], ap, b67);
            }
        }
        __syncthreads();
    }
#pragma unroll
    for (int i = 0; i < 8; i++) {
        int row = row0 + ty * 8 + i;
#pragma unroll
        for (int jp = 0; jp < 4; jp++) {
            float f0, f1;
            UNPACK2(f0, f1, accp[i][jp]);
            int col = col0 + tx * 8 + jp * 2;
            dst[(size_t)row * N + col]     = f0 + __ldg(&bias[col]);
            dst[(size_t)row * N + col + 1] = f1 + __ldg(&bias[col + 1]);
        }
    }
}

// Fused two-layer wavefront GRU scan v2.
// 128 CTAs x 512 threads (1/SM). CTAs 0-63: layer 1; 64-127: layer 2.
// h loads are front-batched into a 64-entry register array before the FMA2
// loop (MLP). L2 computes its h1-dependent half BEFORE waiting on its
// own-layer flags, hiding the wait. Histories t-indexed; monotonic flags.
// SMEM floats: sw 24576 | red 9216 | sb 32
#define FSCAN_SMEM_BYTES ((24576 + 9216 + 32) * 4)

__global__ void __launch_bounds__(512, 1) fused_scan(
    const float* __restrict__ Whh1, const float* __restrict__ bhh1,
    const float* __restrict__ Whr1, const float* __restrict__ bhr1,
    const float* __restrict__ Whh2, const float* __restrict__ bhh2,
    const float* __restrict__ Whr2, const float* __restrict__ bhr2,
    const float* __restrict__ Wxh2, const float* __restrict__ bxh2,
    const float* __restrict__ Wxr2, const float* __restrict__ bxr2)
{
    extern __shared__ __align__(16) float sm[];
    float* sw = sm;            // weights
    float* red = sm + 24576;   // partials: (warp*32+lane)*18
    float* sb = red + 9216;    // biases

    const int tid = threadIdx.x;
    const int warp = tid >> 5, lane = tid & 31;
    const bool isL2 = blockIdx.x >= 64;
    const int c = isL2 ? (int)blockIdx.x - 64 : (int)blockIdx.x;
    const int j0 = c * 8;

    if (!isL2) {
        // sw1[k*24 + gate*8 + jl]; gates z,r,G(Whr)
        for (int i = tid; i < 12288; i += 512) {
            int k = i / 24, rem = i - k * 24;
            int g = rem >> 3, jl = rem & 7;
            float v = (g == 0) ? Whh1[k * 1024 + j0 + jl]
                    : (g == 1) ? Whh1[k * 1024 + 512 + j0 + jl]
                               : Whr1[k * 512 + j0 + jl];
            sw[i] = v;
        }
        if (tid < 24) {
            int g = tid >> 3, jl = tid & 7;
            sb[tid] = (g == 0) ? bhh1[j0 + jl]
                    : (g == 1) ? bhh1[512 + j0 + jl]
                               : bhr1[j0 + jl];
        }
    } else {
        // sw2[k*48 + grp*8 + jl]
        // grps: 0=Wxh_z 1=Wxh_r 2=Wxr(X)  [pass1: h1]
        //       3=Whh_z 4=Whh_r 5=Whr(A)  [pass2: h2]
        for (int i = tid; i < 24576; i += 512) {
            int k = i / 48, rem = i - k * 48;
            int g = rem >> 3, jl = rem & 7;
            float v;
            if (g == 0)      v = Wxh2[k * 1024 + j0 + jl];
            else if (g == 1) v = Wxh2[k * 1024 + 512 + j0 + jl];
            else if (g == 2) v = Wxr2[k * 512 + j0 + jl];
            else if (g == 3) v = Whh2[k * 1024 + j0 + jl];
            else if (g == 4) v = Whh2[k * 1024 + 512 + j0 + jl];
            else             v = Whr2[k * 512 + j0 + jl];
            sw[i] = v;
        }
        if (tid < 32) {
            int g = tid >> 3, jl = tid & 7;
            sb[tid] = (g == 0) ? bxh2[j0 + jl] + bhh2[j0 + jl]
                    : (g == 1) ? bxh2[512 + j0 + jl] + bhh2[512 + j0 + jl]
                    : (g == 2) ? bhr2[j0 + jl]
                               : bxr2[j0 + jl];
        }
    }
    __syncthreads();

    // compute identity: warp = jh(2) x kc(8); lane = batch
    const int jh = warp >> 3, kc = warp & 7, k0 = kc * 64;
    const uint32_t swb = su32(sw) +
        (uint32_t)(isL2 ? (k0 * 192 + jh * 16) : (k0 * 96 + jh * 16));
    // gating identity (tid < 256): jloc = warp&7, b = lane
    const int jloc = warp & 7;
    unsigned* myflag = &g_flags[blockIdx.x * 32];

    float hreg[64];

    for (int t = 0; t < 128; t++) {
        if (!isL2) {
            // ---- layer 1 ----
            if (tid < 64)
                while (ld_acq(&g_flags[tid * 32]) < (unsigned)t) { }
            __syncthreads();

            float pz = 0.f, pr = 0.f, pg = 0.f, hold = 0.f;
            if (tid < 256) {
                int jg = j0 + jloc;
                int m = lane * 128 + t;
                pz = __ldg(&g_xh[(size_t)m * 1024 + jg]);
                pr = __ldg(&g_xh[(size_t)m * 1024 + 512 + jg]);
                pg = __ldg(&g_xr[(size_t)m * 512 + jg]);
                hold = __ldcg(&g_h1[(size_t)t * 16384 + jg * 32 + lane]);
            }

            const float* hb = g_h1 + (size_t)t * 16384 + lane;
#pragma unroll
            for (int k = 0; k < 64; k++)
                hreg[k] = __ldcg(&hb[(k0 + k) * 32]);

            unsigned long long az01 = 0, az23 = 0, ar01 = 0, ar23 = 0;
            unsigned long long aA01 = 0, aA23 = 0;
#pragma unroll
            for (int k = 0; k < 64; k++) {
                unsigned long long hh;
                PACK2(hh, hreg[k], hreg[k]);
                unsigned long long w01, w23;
                uint32_t a = swb + (uint32_t)(k * 96);
                LDS_V2U64(w01, w23, a);
                FMA2(az01, w01, hh); FMA2(az23, w23, hh);
                LDS_V2U64(w01, w23, a + 32);
                FMA2(ar01, w01, hh); FMA2(ar23, w23, hh);
                LDS_V2U64(w01, w23, a + 64);
                FMA2(aA01, w01, hh); FMA2(aA23, w23, hh);
            }
            {
                unsigned long long* rp =
                    (unsigned long long*)&red[(warp * 32 + lane) * 18];
                rp[0] = az01; rp[1] = az23;
                rp[2] = ar01; rp[3] = ar23;
                rp[4] = aA01; rp[5] = aA23;
            }
            __syncthreads();

            if (tid < 256) {
                int jh2 = jloc >> 2, q = jloc & 3;
                float z = 0.f, r = 0.f, A = 0.f;
#pragma unroll
                for (int kc2 = 0; kc2 < 8; kc2++) {
                    const float* qp = &red[((jh2 * 8 + kc2) * 32 + lane) * 18];
                    z += qp[q];
                    r += qp[4 + q];
                    A += qp[8 + q];
                }
                int jg = j0 + jloc;
                z += pz + sb[jloc];
                r += pr + sb[8 + jloc];
                float zs = 1.f / (1.f + __expf(-z));
                float rs = 1.f / (1.f + __expf(-r));
                float gg = tanhf((A + sb[16 + jloc]) * rs + pg);
                float hnew = zs * hold + (1.f - zs) * gg;
                __stcg(&g_h1[(size_t)(t + 1) * 16384 + jg * 32 + lane], hnew);
            }
            __syncthreads();
            if (tid == 0) st_rel(myflag, (unsigned)(t + 1));
        } else {
            // ---- layer 2 ----
            // wait for h1[t+1] (L1 runs ahead: usually instant)
            if (tid < 64)
                while (ld_acq(&g_flags[tid * 32]) < (unsigned)(t + 1)) { }
            __syncthreads();

            // pass 1: h1-dependent streams (Wxh_z, Wxh_r, Wxr)
            const float* hb1 = g_h1 + (size_t)(t + 1) * 16384 + lane;
#pragma unroll
            for (int k = 0; k < 64; k++)
                hreg[k] = __ldcg(&hb1[(k0 + k) * 32]);

            unsigned long long az01 = 0, az23 = 0, ar01 = 0, ar23 = 0;
            unsigned long long aA01 = 0, aA23 = 0, aX01 = 0, aX23 = 0;
#pragma unroll
            for (int k = 0; k < 64; k++) {
                unsigned long long hh;
                PACK2(hh, hreg[k], hreg[k]);
                unsigned long long w01, w23;
                uint32_t a = swb + (uint32_t)(k * 192);
                LDS_V2U64(w01, w23, a);
                FMA2(az01, w01, hh); FMA2(az23, w23, hh);
                LDS_V2U64(w01, w23, a + 32);
                FMA2(ar01, w01, hh); FMA2(ar23, w23, hh);
                LDS_V2U64(w01, w23, a + 64);
                FMA2(aX01, w01, hh); FMA2(aX23, w23, hh);
            }

            // own-layer wait for h2[t] (overlapped by pass 1)
            if (tid < 64)
                while (ld_acq(&g_flags[(64 + tid) * 32]) < (unsigned)t) { }
            __syncthreads();

            float hold = 0.f;
            if (tid < 256)
                hold = __ldcg(&g_h2[(size_t)t * 16384 + (j0 + jloc) * 32 + lane]);

            // pass 2: h2-dependent streams (Whh_z, Whh_r, Whr)
            const float* hb2 = g_h2 + (size_t)t * 16384 + lane;
#pragma unroll
            for (int k = 0; k < 64; k++)
                hreg[k] = __ldcg(&hb2[(k0 + k) * 32]);
#pragma unroll
            for (int k = 0; k < 64; k++) {
                unsigned long long hh;
                PACK2(hh, hreg[k], hreg[k]);
                unsigned long long w01, w23;
                uint32_t a = swb + (uint32_t)(k * 192);
                LDS_V2U64(w01, w23, a + 96);
                FMA2(az01, w01, hh); FMA2(az23, w23, hh);
                LDS_V2U64(w01, w23, a + 128);
                FMA2(ar01, w01, hh); FMA2(ar23, w23, hh);
                LDS_V2U64(w01, w23, a + 160);
                FMA2(aA01, w01, hh); FMA2(aA23, w23, hh);
            }
            {
                unsigned long long* rp =
                    (unsigned long long*)&red[(warp * 32 + lane) * 18];
                rp[0] = az01; rp[1] = az23;
                rp[2] = ar01; rp[3] = ar23;
                rp[4] = aA01; rp[5] = aA23;
                rp[6] = aX01; rp[7] = aX23;
            }
            __syncthreads();

            if (tid < 256) {
                int jh2 = jloc >> 2, q = jloc & 3;
                float z = 0.f, r = 0.f, A = 0.f, X = 0.f;
#pragma unroll
                for (int kc2 = 0; kc2 < 8; kc2++) {
                    const float* qp = &red[((jh2 * 8 + kc2) * 32 + lane) * 18];
                    z += qp[q];
                    r += qp[4 + q];
                    A += qp[8 + q];
                    X += qp[12 + q];
                }
                int jg = j0 + jloc;
                z += sb[jloc];
                r += sb[8 + jloc];
                A += sb[16 + jloc];
                X += sb[24 + jloc];
                float zs = 1.f / (1.f + __expf(-z));
                float rs = 1.f / (1.f + __expf(-r));
                float gg = tanhf(A * rs + X);
                float hnew = zs * hold + (1.f - zs) * gg;
                __stcg(&g_h2[(size_t)(t + 1) * 16384 + jg * 32 + lane], hnew);
            }
            __syncthreads();
            if (tid == 0) st_rel(myflag, (unsigned)(t + 1));
        }
    }
}

// One GRU step with h=0 (reverse branch collapses to two of these).
__global__ void __launch_bounds__(512) rev_step(
    const float* __restrict__ Xext, int ldx, int src_sel,
    const float* __restrict__ Wxh, const float* __restrict__ bxh,
    const float* __restrict__ bhh,
    const float* __restrict__ Wxr, const float* __restrict__ bxr,
    const float* __restrict__ bhr, int dst_trans)
{
    __shared__ float xs[256 * 33];
    const float* X = src_sel ? g_hr1 : Xext;
    int tid = threadIdx.x;
    int jl = tid >> 5, b = tid & 31;
    int j = blockIdx.x * 16 + jl;
    float az = 0.f, ar = 0.f, ag = 0.f;

    for (int k0 = 0; k0 < 512; k0 += 256) {
        __syncthreads();
        int half = tid >> 8, kl = tid & 255;
        for (int b2 = half; b2 < 32; b2 += 2)
            xs[kl * 33 + b2] = X[(size_t)b2 * ldx + k0 + kl];
        __syncthreads();
#pragma unroll 8
        for (int k = 0; k < 256; k++) {
            float xv = xs[k * 33 + b];
            int kk = k0 + k;
            az += xv * __ldg(&Wxh[(size_t)kk * 1024 + j]);
            ar += xv * __ldg(&Wxh[(size_t)kk * 1024 + 512 + j]);
            ag += xv * __ldg(&Wxr[(size_t)kk * 512 + j]);
        }
    }
    float z = 1.f / (1.f + __expf(-(az + __ldg(&bxh[j]) + __ldg(&bhh[j]))));
    float r = 1.f / (1.f + __expf(-(ar + __ldg(&bxh[512 + j]) + __ldg(&bhh[512 + j]))));
    float g = tanhf(__ldg(&bhr[j]) * r + ag + __ldg(&bxr[j]));
    float h = (1.f - z) * g;
    if (dst_trans) g_hr2T[j * 32 + b] = h;
    else           g_hr1[b * 512 + j] = h;
}

// out(32,512) = [h2_final | hr2](32,1024) @ Wfc + bfc
__global__ void __launch_bounds__(512) fc_kernel(
    const float* __restrict__ Wfc, const float* __restrict__ bfc,
    float* __restrict__ out)
{
    int tid = threadIdx.x;
    int jl = tid >> 5, b = tid & 31;
    int j = blockIdx.x * 16 + jl;
    const float* h2f = g_h2 + (size_t)128 * 16384;
    float acc = 0.f;
#pragma unroll 4
    for (int k = 0; k < 512; k++)
        acc += h2f[k * 32 + b] * __ldg(&Wfc[(size_t)k * 512 + j]);
#pragma unroll 4
    for (int k = 0; k < 512; k++)
        acc += g_hr2T[k * 32 + b] * __ldg(&Wfc[(size_t)(512 + k) * 512 + j]);
    out[b * 512 + j] = acc + __ldg(&bfc[j]);
}

extern "C" void kernel_launch(void* const* d_in, const int* in_sizes, int n_in,
                              void* d_out, int out_size) {
    const float* x   = (const float*)d_in[0];
    const float* Wxh = (const float*)d_in[1];
    const float* bxh = (const float*)d_in[2];
    const float* Whh = (const float*)d_in[3];
    const float* bhh = (const float*)d_in[4];
    const float* Wxr = (const float*)d_in[5];
    const float* bxr = (const float*)d_in[6];
    const float* Whr = (const float*)d_in[7];
    const float* bhr = (const float*)d_in[8];
    const float* Wfc = (const float*)d_in[9];
    const float* bfc = (const float*)d_in[10];
    float* out = (float*)d_out;

    cudaFuncSetAttribute(fused_scan,
        cudaFuncAttributeMaxDynamicSharedMemorySize, FSCAN_SMEM_BYTES);

    const size_t WH = 512 * 1024, WR = 512 * 512;

    init_kernel<<<64, 256>>>();

    // layer-1 input projections (slab 0)
    dim3 g1(8, 32), g2(4, 32);
    bulk_gemm<<<g1, 256>>>(x, Wxh, bxh, 1024, 0);
    bulk_gemm<<<g2, 256>>>(x, Wxr, bxr, 512, 1);

    // fused two-layer wavefront scan (layer-1 slab 0, layer-2 slab 2)
    fused_scan<<<128, 512, FSCAN_SMEM_BYTES>>>(
        Whh, bhh, Whr, bhr,
        Whh + 2 * WH, bhh + 2 * 1024, Whr + 2 * WR, bhr + 2 * 512,
        Wxh + 2 * WH, bxh + 2 * 1024, Wxr + 2 * WR, bxr + 2 * 512);

    // reverse branch: two single steps (slabs 1, 3)
    rev_step<<<32, 512>>>(x + 127 * 512, 128 * 512, 0,
        Wxh + 1 * WH, bxh + 1 * 1024, bhh + 1 * 1024,
        Wxr + 1 * WR, bxr + 1 * 512, bhr + 1 * 512, 0);
    rev_step<<<32, 512>>>(nullptr, 512, 1,
        Wxh + 3 * WH, bxh + 3 * 1024, bhh + 3 * 1024,
        Wxr + 3 * WR, bxr + 3 * 512, bhr + 3 * 512, 1);

    fc_kernel<<<32, 512>>>(Wfc, bfc, out);
}

// round 16
// speedup vs baseline: 1.2565x; 1.0222x over previous
#include <cuda_runtime.h>
#include <math.h>
#include <stdint.h>

// B=32, T=128, I=512, H=512, L=2, O=512
__device__ float g_xh[4096 * 1024];   // layer-1 input proj zr, row m=b*128+t
__device__ float g_xr[4096 * 512];    // layer-1 input proj g-input
__device__ float g_h1[129 * 16384];   // h1 history, slab t+1 = h1 after step t
__device__ float g_h2[129 * 16384];   // h2 history, layout [j][b] per slab
__device__ float g_hr1[32 * 512];     // reverse step1 hidden (b, j)
__device__ float g_hr2T[512 * 32];    // reverse step2 hidden (j, b)
__device__ unsigned g_flags[128 * 32]; // per-CTA tick flags (own line)

#define FMA2(acc, a, b) \
    asm("fma.rn.f32x2 %0, %1, %2, %0;" : "+l"(acc) : "l"(a), "l"(b))
#define PACK2(dst, lo, hi) \
    asm("mov.b64 %0, {%1, %2};" : "=l"(dst) : "f"(lo), "f"(hi))
#define UNPACK2(lo, hi, src) \
    asm("mov.b64 {%0, %1}, %2;" : "=f"(lo), "=f"(hi) : "l"(src))
#define LDS_V2U64(a, b, addr) \
    asm("ld.shared.v2.u64 {%0, %1}, [%2];" : "=l"(a), "=l"(b) : "r"(addr))

__device__ __forceinline__ uint32_t su32(const void* p) {
    uint32_t a;
    asm("{ .reg .u64 t; cvta.to.shared.u64 t, %1; cvt.u32.u64 %0, t; }"
        : "=r"(a) : "l"(p));
    return a;
}
__device__ __forceinline__ unsigned ld_acq(const unsigned* p) {
    unsigned v;
    asm volatile("ld.acquire.gpu.u32 %0, [%1];" : "=r"(v) : "l"(p));
    return v;
}
__device__ __forceinline__ void st_rel(unsigned* p, unsigned v) {
    asm volatile("st.release.gpu.u32 [%0], %1;" :: "l"(p), "r"(v));
}

__global__ void init_kernel() {
    unsigned tid = blockIdx.x * blockDim.x + threadIdx.x;
    unsigned n = gridDim.x * blockDim.x;
    for (unsigned i = tid; i < 16384u; i += n) { g_h1[i] = 0.f; g_h2[i] = 0.f; }
    for (unsigned i = tid; i < 4096u; i += n) g_flags[i] = 0u;
}

// C(4096,N) = A(4096,512) @ W(512,N) + bias, f32x2-packed accumulators.
__global__ void __launch_bounds__(256) bulk_gemm(
    const float* __restrict__ A,
    const float* __restrict__ W, const float* __restrict__ bias,
    int N, int dst_sel)
{
    __shared__ __align__(16) float As[16][136];
    __shared__ __align__(16) float Bs[16][136];
    float* dst = dst_sel ? g_xr : g_xh;

    unsigned long long accp[8][4];
#pragma unroll
    for (int i = 0; i < 8; i++)
#pragma unroll
        for (int j = 0; j < 4; j++) accp[i][j] = 0ULL;

    int tid = threadIdx.x, tx = tid & 15, ty = tid >> 4;
    int row0 = blockIdx.y * 128, col0 = blockIdx.x * 128;
    uint32_t bs_base = su32(&Bs[0][0]);

    for (int k0 = 0; k0 < 512; k0 += 16) {
#pragma unroll
        for (int i = 0; i < 2; i++) {
            int t = tid + i * 256;
            int r = t >> 2, kq = (t & 3) << 2;
            float4 v = *(const float4*)&A[(size_t)(row0 + r) * 512 + k0 + kq];
            As[kq + 0][r] = v.x; As[kq + 1][r] = v.y;
            As[kq + 2][r] = v.z; As[kq + 3][r] = v.w;
        }
#pragma unroll
        for (int i = 0; i < 2; i++) {
            int t = tid + i * 256;
            int kr = t >> 5, nq = (t & 31) << 2;
            *(float4*)&Bs[kr][nq] = *(const float4*)&W[(size_t)(k0 + kr) * N + col0 + nq];
        }
        __syncthreads();
#pragma unroll
        for (int kk = 0; kk < 16; kk++) {
            float a[8];
            *(float4*)&a[0] = *(float4*)&As[kk][ty * 8];
            *(float4*)&a[4] = *(float4*)&As[kk][ty * 8 + 4];
            unsigned long long b01, b23, b45, b67;
            uint32_t ba = bs_base + (uint32_t)(kk * 136 + tx * 8) * 4u;
            LDS_V2U64(b01, b23, ba);
            LDS_V2U64(b45, b67, ba + 16);
#pragma unroll
            for (int i = 0; i < 8; i++) {
                unsigned long long ap;
                PACK2(ap, a[i], a[i]);
                FMA2(accp[i][0], ap, b01);
                FMA2(accp[i][1], ap, b23);
                FMA2(accp[i][2], ap, b45);
                FMA2(accp[i][3], ap, b67);
            }
        }
        __syncthreads();
    }
#pragma unroll
    for (int i = 0; i < 8; i++) {
        int row = row0 + ty * 8 + i;
#pragma unroll
        for (int jp = 0; jp < 4; jp++) {
            float f0, f1;
            UNPACK2(f0, f1, accp[i][jp]);
            int col = col0 + tx * 8 + jp * 2;
            dst[(size_t)row * N + col]     = f0 + __ldg(&bias[col]);
            dst[(size_t)row * N + col + 1] = f1 + __ldg(&bias[col + 1]);
        }
    }
}

// Uniform dual-role fused scan: 128 CTAs x 512 threads, 1/SM.
// Every CTA owns 4 j-cols of L1 AND the same 4 j-cols of L2.
// Tick i (0..129): L1 step i (if i<128) + L2 step i-2 (if i>=2).
// One 128-flag wait per tick covers h1[i], h1[i-1], h2[i-2].
// Warp = 32-k chunk (16 warps); lane = batch. 9 weight streams per k:
//   0..2: Whh1_z, Whh1_r, Whr1     (x h1[i])
//   3..5: Whh2_z, Whh2_r, Whr2     (x h2[i-2])
//   6..8: Wxh2_z, Wxh2_r, Wxr2     (x h1[i-1])
// SMEM floats: sw 512*36=18432 | red 16*32*30=15360 | sb 32
#define FSCAN_SMEM_BYTES ((18432 + 15360 + 32) * 4)

__global__ void __launch_bounds__(512, 1) fused_scan(
    const float* __restrict__ Whh1, const float* __restrict__ bhh1,
    const float* __restrict__ Whr1, const float* __restrict__ bhr1,
    const float* __restrict__ Whh2, const float* __restrict__ bhh2,
    const float* __restrict__ Whr2, const float* __restrict__ bhr2,
    const float* __restrict__ Wxh2, const float* __restrict__ bxh2,
    const float* __restrict__ Wxr2, const float* __restrict__ bxr2)
{
    extern __shared__ __align__(16) float sm[];
    float* sw = sm;            // [k][stream*4 + jl], 36 floats per k
    float* red = sm + 18432;   // [(warp*32+lane)*30 + 0..27]
    float* sb = red + 15360;   // 28 biases

    const int tid = threadIdx.x;
    const int warp = tid >> 5, lane = tid & 31;
    const int j0 = blockIdx.x * 4;

    for (int i = tid; i < 18432; i += 512) {
        int k = i / 36, rem = i - k * 36;
        int s = rem >> 2, jl = rem & 3;
        int j = j0 + jl;
        float v;
        switch (s) {
            case 0: v = Whh1[k * 1024 + j]; break;
            case 1: v = Whh1[k * 1024 + 512 + j]; break;
            case 2: v = Whr1[k * 512 + j]; break;
            case 3: v = Whh2[k * 1024 + j]; break;
            case 4: v = Whh2[k * 1024 + 512 + j]; break;
            case 5: v = Whr2[k * 512 + j]; break;
            case 6: v = Wxh2[k * 1024 + j]; break;
            case 7: v = Wxh2[k * 1024 + 512 + j]; break;
            default: v = Wxr2[k * 512 + j]; break;
        }
        sw[i] = v;
    }
    if (tid < 28) {
        int s = tid >> 2, jl = tid & 3;
        int j = j0 + jl;
        float v;
        switch (s) {
            case 0: v = bhh1[j]; break;
            case 1: v = bhh1[512 + j]; break;
            case 2: v = bhr1[j]; break;
            case 3: v = bxh2[j] + bhh2[j]; break;
            case 4: v = bxh2[512 + j] + bhh2[512 + j]; break;
            case 5: v = bhr2[j]; break;
            default: v = bxr2[j]; break;
        }
        sb[tid] = v;
    }
    __syncthreads();

    const uint32_t swb0 = su32(sw) + (uint32_t)(warp * 32) * 144u;
    // gating identity (tid<256): jr = tid>>5 (0..7), b = lane
    const int jr = warp;                // 0..3 -> L1 j, 4..7 -> L2 j
    unsigned* myflag = &g_flags[blockIdx.x * 32];

    float hreg[32];

    for (int i = 0; i < 130; i++) {
        // single wait: all CTAs done tick i-1
        if (tid < 128)
            while (ld_acq(&g_flags[tid * 32]) < (unsigned)i) { }
        __syncthreads();

        const int s1 = (i < 128) ? i : 128;          // h1[i] slab
        const int s2 = (i >= 2) ? (i - 2) : 0;       // h2[i-2] slab
        const int s3 = (i >= 1) ? (i - 1) : 0;       // h1[i-1] slab

        // prefetch gating inputs
        float pz = 0.f, pr = 0.f, pg = 0.f, hold = 0.f;
        if (tid < 256) {
            if (jr < 4) {
                int jg = j0 + jr;
                int m = lane * 128 + ((i < 128) ? i : 127);
                pz = __ldg(&g_xh[(size_t)m * 1024 + jg]);
                pr = __ldg(&g_xh[(size_t)m * 1024 + 512 + jg]);
                pg = __ldg(&g_xr[(size_t)m * 512 + jg]);
                hold = __ldcg(&g_h1[(size_t)s1 * 16384 + jg * 32 + lane]);
            } else {
                int jg = j0 + (jr - 4);
                hold = __ldcg(&g_h2[(size_t)s2 * 16384 + jg * 32 + lane]);
            }
        }

        unsigned long long l1z0 = 0, l1z1 = 0, l1r0 = 0, l1r1 = 0;
        unsigned long long l1A0 = 0, l1A1 = 0;
        unsigned long long l2z0 = 0, l2z1 = 0, l2r0 = 0, l2r1 = 0;
        unsigned long long l2A0 = 0, l2A1 = 0, l2X0 = 0, l2X1 = 0;

        // ---- loop 1: h1[i] x L1 weights (streams 0..2) ----
        {
            const float* hb = g_h1 + (size_t)s1 * 16384 + lane;
#pragma unroll
            for (int k = 0; k < 32; k++)
                hreg[k] = __ldcg(&hb[(warp * 32 + k) * 32]);
#pragma unroll
            for (int k = 0; k < 32; k++) {
                unsigned long long hh, w01, w23;
                PACK2(hh, hreg[k], hreg[k]);
                uint32_t a = swb0 + (uint32_t)(k * 144);
                LDS_V2U64(w01, w23, a);
                FMA2(l1z0, w01, hh); FMA2(l1z1, w23, hh);
                LDS_V2U64(w01, w23, a + 16);
                FMA2(l1r0, w01, hh); FMA2(l1r1, w23, hh);
                LDS_V2U64(w01, w23, a + 32);
                FMA2(l1A0, w01, hh); FMA2(l1A1, w23, hh);
            }
        }
        // ---- loop 2: h2[i-2] x L2 recurrent weights (streams 3..5) ----
        {
            const float* hb = g_h2 + (size_t)s2 * 16384 + lane;
#pragma unroll
            for (int k = 0; k < 32; k++)
                hreg[k] = __ldcg(&hb[(warp * 32 + k) * 32]);
#pragma unroll
            for (int k = 0; k < 32; k++) {
                unsigned long long hh, w01, w23;
                PACK2(hh, hreg[k], hreg[k]);
                uint32_t a = swb0 + (uint32_t)(k * 144);
                LDS_V2U64(w01, w23, a + 48);
                FMA2(l2z0, w01, hh); FMA2(l2z1, w23, hh);
                LDS_V2U64(w01, w23, a + 64);
                FMA2(l2r0, w01, hh); FMA2(l2r1, w23, hh);
                LDS_V2U64(w01, w23, a + 80);
                FMA2(l2A0, w01, hh); FMA2(l2A1, w23, hh);
            }
        }
        // ---- loop 3: h1[i-1] x L2 input weights (streams 6..8) ----
        {
            const float* hb = g_h1 + (size_t)s3 * 16384 + lane;
#pragma unroll
            for (int k = 0; k < 32; k++)
                hreg[k] = __ldcg(&hb[(warp * 32 + k) * 32]);
#pragma unroll
            for (int k = 0; k < 32; k++) {
                unsigned long long hh, w01, w23;
                PACK2(hh, hreg[k], hreg[k]);
                uint32_t a = swb0 + (uint32_t)(k * 144);
                LDS_V2U64(w01, w23, a + 96);
                FMA2(l2z0, w01, hh); FMA2(l2z1, w23, hh);
                LDS_V2U64(w01, w23, a + 112);
                FMA2(l2r0, w01, hh); FMA2(l2r1, w23, hh);
                LDS_V2U64(w01, w23, a + 128);
                FMA2(l2X0, w01, hh); FMA2(l2X1, w23, hh);
            }
        }
        {
            unsigned long long* rp =
                (unsigned long long*)&red[(warp * 32 + lane) * 30];
            rp[0] = l1z0; rp[1] = l1z1; rp[2] = l1r0; rp[3] = l1r1;
            rp[4] = l1A0; rp[5] = l1A1;
            rp[6] = l2z0; rp[7] = l2z1; rp[8] = l2r0; rp[9] = l2r1;
            rp[10] = l2A0; rp[11] = l2A1; rp[12] = l2X0; rp[13] = l2X1;
        }
        __syncthreads();

        if (tid < 256) {
            if (jr < 4 && i < 128) {
                float z = 0.f, r = 0.f, A = 0.f;
#pragma unroll
                for (int kc = 0; kc < 16; kc++) {
                    const float* q = &red[(kc * 32 + lane) * 30];
                    z += q[jr];
                    r += q[4 + jr];
                    A += q[8 + jr];
                }
                int jg = j0 + jr;
                z += pz + sb[jr];
                r += pr + sb[4 + jr];
                float zs = 1.f / (1.f + __expf(-z));
                float rs = 1.f / (1.f + __expf(-r));
                float gg = tanhf((A + sb[8 + jr]) * rs + pg);
                float hnew = zs * hold + (1.f - zs) * gg;
                __stcg(&g_h1[(size_t)(i + 1) * 16384 + jg * 32 + lane], hnew);
            } else if (jr >= 4 && i >= 2) {
                int jl = jr - 4;
                float z = 0.f, r = 0.f, A = 0.f, X = 0.f;
#pragma unroll
                for (int kc = 0; kc < 16; kc++) {
                    const float* q = &red[(kc * 32 + lane) * 30];
                    z += q[12 + jl];
                    r += q[16 + jl];
                    A += q[20 + jl];
                    X += q[24 + jl];
                }
                int jg = j0 + jl;
                z += sb[12 + jl];
                r += sb[16 + jl];
                float zs = 1.f / (1.f + __expf(-z));
                float rs = 1.f / (1.f + __expf(-r));
                float gg = tanhf((A + sb[20 + jl]) * rs + X + sb[24 + jl]);
                float hnew = zs * hold + (1.f - zs) * gg;
                __stcg(&g_h2[(size_t)(i - 1) * 16384 + jg * 32 + lane], hnew);
            }
        }
        __syncthreads();
        if (tid == 0) st_rel(myflag, (unsigned)(i + 1));
    }
}

// One GRU step with h=0 (reverse branch collapses to two of these).
__global__ void __launch_bounds__(512) rev_step(
    const float* __restrict__ Xext, int ldx, int src_sel,
    const float* __restrict__ Wxh, const float* __restrict__ bxh,
    const float* __restrict__ bhh,
    const float* __restrict__ Wxr, const float* __restrict__ bxr,
    const float* __restrict__ bhr, int dst_trans)
{
    __shared__ float xs[256 * 33];
    const float* X = src_sel ? g_hr1 : Xext;
    int tid = threadIdx.x;
    int jl = tid >> 5, b = tid & 31;
    int j = blockIdx.x * 16 + jl;
    float az = 0.f, ar = 0.f, ag = 0.f;

    for (int k0 = 0; k0 < 512; k0 += 256) {
        __syncthreads();
        int half = tid >> 8, kl = tid & 255;
        for (int b2 = half; b2 < 32; b2 += 2)
            xs[kl * 33 + b2] = X[(size_t)b2 * ldx + k0 + kl];
        __syncthreads();
#pragma unroll 8
        for (int k = 0; k < 256; k++) {
            float xv = xs[k * 33 + b];
            int kk = k0 + k;
            az += xv * __ldg(&Wxh[(size_t)kk * 1024 + j]);
            ar += xv * __ldg(&Wxh[(size_t)kk * 1024 + 512 + j]);
            ag += xv * __ldg(&Wxr[(size_t)kk * 512 + j]);
        }
    }
    float z = 1.f / (1.f + __expf(-(az + __ldg(&bxh[j]) + __ldg(&bhh[j]))));
    float r = 1.f / (1.f + __expf(-(ar + __ldg(&bxh[512 + j]) + __ldg(&bhh[512 + j]))));
    float g = tanhf(__ldg(&bhr[j]) * r + ag + __ldg(&bxr[j]));
    float h = (1.f - z) * g;
    if (dst_trans) g_hr2T[j * 32 + b] = h;
    else           g_hr1[b * 512 + j] = h;
}

// out(32,512) = [h2_final | hr2](32,1024) @ Wfc + bfc
__global__ void __launch_bounds__(512) fc_kernel(
    const float* __restrict__ Wfc, const float* __restrict__ bfc,
    float* __restrict__ out)
{
    int tid = threadIdx.x;
    int jl = tid >> 5, b = tid & 31;
    int j = blockIdx.x * 16 + jl;
    const float* h2f = g_h2 + (size_t)128 * 16384;
    float acc = 0.f;
#pragma unroll 4
    for (int k = 0; k < 512; k++)
        acc += h2f[k * 32 + b] * __ldg(&Wfc[(size_t)k * 512 + j]);
#pragma unroll 4
    for (int k = 0; k < 512; k++)
        acc += g_hr2T[k * 32 + b] * __ldg(&Wfc[(size_t)(512 + k) * 512 + j]);
    out[b * 512 + j] = acc + __ldg(&bfc[j]);
}

extern "C" void kernel_launch(void* const* d_in, const int* in_sizes, int n_in,
                              void* d_out, int out_size) {
    const float* x   = (const float*)d_in[0];
    const float* Wxh = (const float*)d_in[1];
    const float* bxh = (const float*)d_in[2];
    const float* Whh = (const float*)d_in[3];
    const float* bhh = (const float*)d_in[4];
    const float* Wxr = (const float*)d_in[5];
    const float* bxr = (const float*)d_in[6];
    const float* Whr = (const float*)d_in[7];
    const float* bhr = (const float*)d_in[8];
    const float* Wfc = (const float*)d_in[9];
    const float* bfc = (const float*)d_in[10];
    float* out = (float*)d_out;

    cudaFuncSetAttribute(fused_scan,
        cudaFuncAttributeMaxDynamicSharedMemorySize, FSCAN_SMEM_BYTES);

    const size_t WH = 512 * 1024, WR = 512 * 512;

    init_kernel<<<64, 256>>>();

    // layer-1 input projections (slab 0)
    dim3 g1(8, 32), g2(4, 32);
    bulk_gemm<<<g1, 256>>>(x, Wxh, bxh, 1024, 0);
    bulk_gemm<<<g2, 256>>>(x, Wxr, bxr, 512, 1);

    // uniform dual-role fused scan (L1 slab 0, L2 slab 2)
    fused_scan<<<128, 512, FSCAN_SMEM_BYTES>>>(
        Whh, bhh, Whr, bhr,
        Whh + 2 * WH, bhh + 2 * 1024, Whr + 2 * WR, bhr + 2 * 512,
        Wxh + 2 * WH, bxh + 2 * 1024, Wxr + 2 * WR, bxr + 2 * 512);

    // reverse branch: two single steps (slabs 1, 3)
    rev_step<<<32, 512>>>(x + 127 * 512, 128 * 512, 0,
        Wxh + 1 * WH, bxh + 1 * 1024, bhh + 1 * 1024,
        Wxr + 1 * WR, bxr + 1 * 512, bhr + 1 * 512, 0);
    rev_step<<<32, 512>>>(nullptr, 512, 1,
        Wxh + 3 * WH, bxh + 3 * 1024, bhh + 3 * 1024,
        Wxr + 3 * WR, bxr + 3 * 512, bhr + 3 * 512, 1);

    fc_kernel<<<32, 512>>>(Wfc, bfc, out);
}

// round 17
// speedup vs baseline: 1.2928x; 1.0289x over previous
#include <cuda_runtime.h>
#include <math.h>
#include <stdint.h>

// B=32, T=128, I=512, H=512, L=2, O=512
__device__ float g_xh[4096 * 1024];   // layer-1 input proj zr, row m=b*128+t
__device__ float g_xr[4096 * 512];    // layer-1 input proj g-input
__device__ float g_h1[129 * 16384];   // h1 history, slab t+1 = h1 after step t
__device__ float g_h2[129 * 16384];   // h2 history, layout [j][b] per slab
__device__ float g_hr1[32 * 512];     // reverse step1 hidden (b, j)
__device__ float g_hr2T[512 * 32];    // reverse step2 hidden (j, b)
__device__ unsigned g_flags[128 * 32]; // per-CTA tick flags (own line)

#define FMA2(acc, a, b) \
    asm("fma.rn.f32x2 %0, %1, %2, %0;" : "+l"(acc) : "l"(a), "l"(b))
#define PACK2(dst, lo, hi) \
    asm("mov.b64 %0, {%1, %2};" : "=l"(dst) : "f"(lo), "f"(hi))
#define UNPACK2(lo, hi, src) \
    asm("mov.b64 {%0, %1}, %2;" : "=f"(lo), "=f"(hi) : "l"(src))
#define LDS_V2U64(a, b, addr) \
    asm("ld.shared.v2.u64 {%0, %1}, [%2];" : "=l"(a), "=l"(b) : "r"(addr))

__device__ __forceinline__ uint32_t su32(const void* p) {
    uint32_t a;
    asm("{ .reg .u64 t; cvta.to.shared.u64 t, %1; cvt.u32.u64 %0, t; }"
        : "=r"(a) : "l"(p));
    return a;
}
__device__ __forceinline__ unsigned ld_acq(const unsigned* p) {
    unsigned v;
    asm volatile("ld.acquire.gpu.u32 %0, [%1];" : "=r"(v) : "l"(p));
    return v;
}
__device__ __forceinline__ void st_rel(unsigned* p, unsigned v) {
    asm volatile("st.release.gpu.u32 [%0], %1;" :: "l"(p), "r"(v));
}

__global__ void init_kernel() {
    unsigned tid = blockIdx.x * blockDim.x + threadIdx.x;
    unsigned n = gridDim.x * blockDim.x;
    for (unsigned i = tid; i < 16384u; i += n) { g_h1[i] = 0.f; g_h2[i] = 0.f; }
    for (unsigned i = tid; i < 4096u; i += n) g_flags[i] = 0u;
}

// C(4096,N) = A(4096,512) @ W(512,N) + bias, f32x2-packed accumulators.
__global__ void __launch_bounds__(256) bulk_gemm(
    const float* __restrict__ A,
    const float* __restrict__ W, const float* __restrict__ bias,
    int N, int dst_sel)
{
    __shared__ __align__(16) float As[16][136];
    __shared__ __align__(16) float Bs[16][136];
    float* dst = dst_sel ? g_xr : g_xh;

    unsigned long long accp[8][4];
#pragma unroll
    for (int i = 0; i < 8; i++)
#pragma unroll
        for (int j = 0; j < 4; j++) accp[i][j] = 0ULL;

    int tid = threadIdx.x, tx = tid & 15, ty = tid >> 4;
    int row0 = blockIdx.y * 128, col0 = blockIdx.x * 128;
    uint32_t bs_base = su32(&Bs[0][0]);

    for (int k0 = 0; k0 < 512; k0 += 16) {
#pragma unroll
        for (int i = 0; i < 2; i++) {
            int t = tid + i * 256;
            int r = t >> 2, kq = (t & 3) << 2;
            float4 v = *(const float4*)&A[(size_t)(row0 + r) * 512 + k0 + kq];
            As[kq + 0][r] = v.x; As[kq + 1][r] = v.y;
            As[kq + 2][r] = v.z; As[kq + 3][r] = v.w;
        }
#pragma unroll
        for (int i = 0; i < 2; i++) {
            int t = tid + i * 256;
            int kr = t >> 5, nq = (t & 31) << 2;
            *(float4*)&Bs[kr][nq] = *(const float4*)&W[(size_t)(k0 + kr) * N + col0 + nq];
        }
        __syncthreads();
#pragma unroll
        for (int kk = 0; kk < 16; kk++) {
            float a[8];
            *(float4*)&a[0] = *(float4*)&As[kk][ty * 8];
            *(float4*)&a[4] = *(float4*)&As[kk][ty * 8 + 4];
            unsigned long long b01, b23, b45, b67;
            uint32_t ba = bs_base + (uint32_t)(kk * 136 + tx * 8) * 4u;
            LDS_V2U64(b01, b23, ba);
            LDS_V2U64(b45, b67, ba + 16);
#pragma unroll
            for (int i = 0; i < 8; i++) {
                unsigned long long ap;
                PACK2(ap, a[i], a[i]);
                FMA2(accp[i][0], ap, b01);
                FMA2(accp[i][1], ap, b23);
                FMA2(accp[i][2], ap, b45);
                FMA2(accp[i][3], ap, b67);
            }
        }
        __syncthreads();
    }
#pragma unroll
    for (int i = 0; i < 8; i++) {
        int row = row0 + ty * 8 + i;
#pragma unroll
        for (int jp = 0; jp < 4; jp++) {
            float f0, f1;
            UNPACK2(f0, f1, accp[i][jp]);
            int col = col0 + tx * 8 + jp * 2;
            dst[(size_t)row * N + col]     = f0 + __ldg(&bias[col]);
            dst[(size_t)row * N + col + 1] = f1 + __ldg(&bias[col + 1]);
        }
    }
}

// Uniform dual-role fused scan v2: 128 CTAs x 1024 threads (32 warps), 1/SM.
// Every CTA owns 4 j-cols of both layers. Tick i: L1 step i + L2 step i-2.
// Warp = 16-k chunk; lane = batch. 9 weight streams per k (same as R16).
// Loop 3 (h1[i-1] x L2-input) runs BEFORE the flag wait (data is one tick
// old), overlapping flag propagation with 1/3 of the compute.
// SMEM floats: sw 18432 | red 1024*30=30720 | sb 32
#define FSCAN_SMEM_BYTES ((18432 + 30720 + 32) * 4)

__global__ void __launch_bounds__(1024, 1) fused_scan(
    const float* __restrict__ Whh1, const float* __restrict__ bhh1,
    const float* __restrict__ Whr1, const float* __restrict__ bhr1,
    const float* __restrict__ Whh2, const float* __restrict__ bhh2,
    const float* __restrict__ Whr2, const float* __restrict__ bhr2,
    const float* __restrict__ Wxh2, const float* __restrict__ bxh2,
    const float* __restrict__ Wxr2, const float* __restrict__ bxr2)
{
    extern __shared__ __align__(16) float sm[];
    float* sw = sm;            // [k][stream*4 + jl], 36 floats per k
    float* red = sm + 18432;   // [tid*30 + 0..27]
    float* sb = red + 30720;   // 28 biases

    const int tid = threadIdx.x;
    const int warp = tid >> 5, lane = tid & 31;
    const int j0 = blockIdx.x * 4;

    for (int i = tid; i < 18432; i += 1024) {
        int k = i / 36, rem = i - k * 36;
        int s = rem >> 2, jl = rem & 3;
        int j = j0 + jl;
        float v;
        switch (s) {
            case 0: v = Whh1[k * 1024 + j]; break;
            case 1: v = Whh1[k * 1024 + 512 + j]; break;
            case 2: v = Whr1[k * 512 + j]; break;
            case 3: v = Whh2[k * 1024 + j]; break;
            case 4: v = Whh2[k * 1024 + 512 + j]; break;
            case 5: v = Whr2[k * 512 + j]; break;
            case 6: v = Wxh2[k * 1024 + j]; break;
            case 7: v = Wxh2[k * 1024 + 512 + j]; break;
            default: v = Wxr2[k * 512 + j]; break;
        }
        sw[i] = v;
    }
    if (tid < 28) {
        int s = tid >> 2, jl = tid & 3;
        int j = j0 + jl;
        float v;
        switch (s) {
            case 0: v = bhh1[j]; break;
            case 1: v = bhh1[512 + j]; break;
            case 2: v = bhr1[j]; break;
            case 3: v = bxh2[j] + bhh2[j]; break;
            case 4: v = bxh2[512 + j] + bhh2[512 + j]; break;
            case 5: v = bhr2[j]; break;
            default: v = bxr2[j]; break;
        }
        sb[tid] = v;
    }
    __syncthreads();

    const uint32_t swb0 = su32(sw) + (uint32_t)(warp * 16) * 144u;
    const int jr = warp;                // gating id for tid<256
    unsigned* myflag = &g_flags[blockIdx.x * 32];

    float hreg[8];

    for (int i = 0; i < 130; i++) {
        const bool doL1 = (i < 128);
        const bool doL2 = (i >= 2);
        const int s1 = doL1 ? i : 128;
        const int s2 = doL2 ? (i - 2) : 0;
        const int s3 = doL2 ? (i - 1) : 0;

        // static prefetches (pre-wait)
        float pz = 0.f, pr = 0.f, pg = 0.f, hold = 0.f;
        if (tid < 256 && jr < 4 && doL1) {
            int jg = j0 + jr;
            int m = lane * 128 + i;
            pz = __ldg(&g_xh[(size_t)m * 1024 + jg]);
            pr = __ldg(&g_xh[(size_t)m * 1024 + 512 + jg]);
            pg = __ldg(&g_xr[(size_t)m * 512 + jg]);
        }

        unsigned long long l1z0 = 0, l1z1 = 0, l1r0 = 0, l1r1 = 0;
        unsigned long long l1A0 = 0, l1A1 = 0;
        unsigned long long l2z0 = 0, l2z1 = 0, l2r0 = 0, l2r1 = 0;
        unsigned long long l2A0 = 0, l2A1 = 0, l2X0 = 0, l2X1 = 0;

        // ---- loop 3 (PRE-WAIT): h1[i-1] x L2 input weights (streams 6..8)
        if (doL2) {
            const float* hb = g_h1 + (size_t)s3 * 16384 + lane;
#pragma unroll
            for (int kb = 0; kb < 2; kb++) {
#pragma unroll
                for (int k = 0; k < 8; k++)
                    hreg[k] = __ldcg(&hb[(warp * 16 + kb * 8 + k) * 32]);
#pragma unroll
                for (int k = 0; k < 8; k++) {
                    unsigned long long hh, w01, w23;
                    PACK2(hh, hreg[k], hreg[k]);
                    uint32_t a = swb0 + (uint32_t)((kb * 8 + k) * 144);
                    LDS_V2U64(w01, w23, a + 96);
                    FMA2(l2z0, w01, hh); FMA2(l2z1, w23, hh);
                    LDS_V2U64(w01, w23, a + 112);
                    FMA2(l2r0, w01, hh); FMA2(l2r1, w23, hh);
                    LDS_V2U64(w01, w23, a + 128);
                    FMA2(l2X0, w01, hh); FMA2(l2X1, w23, hh);
                }
            }
        }

        // single wait: all CTAs done tick i-1
        if (tid < 128)
            while (ld_acq(&g_flags[tid * 32]) < (unsigned)i) { }
        __syncthreads();

        if (tid < 256) {
            if (jr < 4) {
                if (doL1)
                    hold = __ldcg(&g_h1[(size_t)s1 * 16384 + (j0 + jr) * 32 + lane]);
            } else if (doL2) {
                hold = __ldcg(&g_h2[(size_t)s2 * 16384 + (j0 + jr - 4) * 32 + lane]);
            }
        }

        // ---- loop 1: h1[i] x L1 weights (streams 0..2)
        if (doL1) {
            const float* hb = g_h1 + (size_t)s1 * 16384 + lane;
#pragma unroll
            for (int kb = 0; kb < 2; kb++) {
#pragma unroll
                for (int k = 0; k < 8; k++)
                    hreg[k] = __ldcg(&hb[(warp * 16 + kb * 8 + k) * 32]);
#pragma unroll
                for (int k = 0; k < 8; k++) {
                    unsigned long long hh, w01, w23;
                    PACK2(hh, hreg[k], hreg[k]);
                    uint32_t a = swb0 + (uint32_t)((kb * 8 + k) * 144);
                    LDS_V2U64(w01, w23, a);
                    FMA2(l1z0, w01, hh); FMA2(l1z1, w23, hh);
                    LDS_V2U64(w01, w23, a + 16);
                    FMA2(l1r0, w01, hh); FMA2(l1r1, w23, hh);
                    LDS_V2U64(w01, w23, a + 32);
                    FMA2(l1A0, w01, hh); FMA2(l1A1, w23, hh);
                }
            }
        }
        // ---- loop 2: h2[i-2] x L2 recurrent weights (streams 3..5)
        if (doL2) {
            const float* hb = g_h2 + (size_t)s2 * 16384 + lane;
#pragma unroll
            for (int kb = 0; kb < 2; kb++) {
#pragma unroll
                for (int k = 0; k < 8; k++)
                    hreg[k] = __ldcg(&hb[(warp * 16 + kb * 8 + k) * 32]);
#pragma unroll
                for (int k = 0; k < 8; k++) {
                    unsigned long long hh, w01, w23;
                    PACK2(hh, hreg[k], hreg[k]);
                    uint32_t a = swb0 + (uint32_t)((kb * 8 + k) * 144);
                    LDS_V2U64(w01, w23, a + 48);
                    FMA2(l2z0, w01, hh); FMA2(l2z1, w23, hh);
                    LDS_V2U64(w01, w23, a + 64);
                    FMA2(l2r0, w01, hh); FMA2(l2r1, w23, hh);
                    LDS_V2U64(w01, w23, a + 80);
                    FMA2(l2A0, w01, hh); FMA2(l2A1, w23, hh);
                }
            }
        }
        {
            unsigned long long* rp = (unsigned long long*)&red[tid * 30];
            rp[0] = l1z0; rp[1] = l1z1; rp[2] = l1r0; rp[3] = l1r1;
            rp[4] = l1A0; rp[5] = l1A1;
            rp[6] = l2z0; rp[7] = l2z1; rp[8] = l2r0; rp[9] = l2r1;
            rp[10] = l2A0; rp[11] = l2A1; rp[12] = l2X0; rp[13] = l2X1;
        }
        __syncthreads();

        if (tid < 256) {
            if (jr < 4 && doL1) {
                float z = 0.f, r = 0.f, A = 0.f;
#pragma unroll
                for (int w = 0; w < 32; w++) {
                    const float* q = &red[(w * 32 + lane) * 30];
                    z += q[jr];
                    r += q[4 + jr];
                    A += q[8 + jr];
                }
                int jg = j0 + jr;
                z += pz + sb[jr];
                r += pr + sb[4 + jr];
                float zs = 1.f / (1.f + __expf(-z));
                float rs = 1.f / (1.f + __expf(-r));
                float gg = tanhf((A + sb[8 + jr]) * rs + pg);
                float hnew = zs * hold + (1.f - zs) * gg;
                __stcg(&g_h1[(size_t)(i + 1) * 16384 + jg * 32 + lane], hnew);
            } else if (jr >= 4 && doL2) {
                int jl = jr - 4;
                float z = 0.f, r = 0.f, A = 0.f, X = 0.f;
#pragma unroll
                for (int w = 0; w < 32; w++) {
                    const float* q = &red[(w * 32 + lane) * 30];
                    z += q[12 + jl];
                    r += q[16 + jl];
                    A += q[20 + jl];
                    X += q[24 + jl];
                }
                int jg = j0 + jl;
                z += sb[12 + jl];
                r += sb[16 + jl];
                float zs = 1.f / (1.f + __expf(-z));
                float rs = 1.f / (1.f + __expf(-r));
                float gg = tanhf((A + sb[20 + jl]) * rs + X + sb[24 + jl]);
                float hnew = zs * hold + (1.f - zs) * gg;
                __stcg(&g_h2[(size_t)(i - 1) * 16384 + jg * 32 + lane], hnew);
            }
        }
        __syncthreads();
        if (tid == 0) st_rel(myflag, (unsigned)(i + 1));
    }
}

// One GRU step with h=0 (reverse branch collapses to two of these).
__global__ void __launch_bounds__(512) rev_step(
    const float* __restrict__ Xext, int ldx, int src_sel,
    const float* __restrict__ Wxh, const float* __restrict__ bxh,
    const float* __restrict__ bhh,
    const float* __restrict__ Wxr, const float* __restrict__ bxr,
    const float* __restrict__ bhr, int dst_trans)
{
    __shared__ float xs[256 * 33];
    const float* X = src_sel ? g_hr1 : Xext;
    int tid = threadIdx.x;
    int jl = tid >> 5, b = tid & 31;
    int j = blockIdx.x * 16 + jl;
    float az = 0.f, ar = 0.f, ag = 0.f;

    for (int k0 = 0; k0 < 512; k0 += 256) {
        __syncthreads();
        int half = tid >> 8, kl = tid & 255;
        for (int b2 = half; b2 < 32; b2 += 2)
            xs[kl * 33 + b2] = X[(size_t)b2 * ldx + k0 + kl];
        __syncthreads();
#pragma unroll 8
        for (int k = 0; k < 256; k++) {
            float xv = xs[k * 33 + b];
            int kk = k0 + k;
            az += xv * __ldg(&Wxh[(size_t)kk * 1024 + j]);
            ar += xv * __ldg(&Wxh[(size_t)kk * 1024 + 512 + j]);
            ag += xv * __ldg(&Wxr[(size_t)kk * 512 + j]);
        }
    }
    float z = 1.f / (1.f + __expf(-(az + __ldg(&bxh[j]) + __ldg(&bhh[j]))));
    float r = 1.f / (1.f + __expf(-(ar + __ldg(&bxh[512 + j]) + __ldg(&bhh[512 + j]))));
    float g = tanhf(__ldg(&bhr[j]) * r + ag + __ldg(&bxr[j]));
    float h = (1.f - z) * g;
    if (dst_trans) g_hr2T[j * 32 + b] = h;
    else           g_hr1[b * 512 + j] = h;
}

// out(32,512) = [h2_final | hr2](32,1024) @ Wfc + bfc
__global__ void __launch_bounds__(512) fc_kernel(
    const float* __restrict__ Wfc, const float* __restrict__ bfc,
    float* __restrict__ out)
{
    int tid = threadIdx.x;
    int jl = tid >> 5, b = tid & 31;
    int j = blockIdx.x * 16 + jl;
    const float* h2f = g_h2 + (size_t)128 * 16384;
    float acc = 0.f;
#pragma unroll 4
    for (int k = 0; k < 512; k++)
        acc += h2f[k * 32 + b] * __ldg(&Wfc[(size_t)k * 512 + j]);
#pragma unroll 4
    for (int k = 0; k < 512; k++)
        acc += g_hr2T[k * 32 + b] * __ldg(&Wfc[(size_t)(512 + k) * 512 + j]);
    out[b * 512 + j] = acc + __ldg(&bfc[j]);
}

extern "C" void kernel_launch(void* const* d_in, const int* in_sizes, int n_in,
                              void* d_out, int out_size) {
    const float* x   = (const float*)d_in[0];
    const float* Wxh = (const float*)d_in[1];
    const float* bxh = (const float*)d_in[2];
    const float* Whh = (const float*)d_in[3];
    const float* bhh = (const float*)d_in[4];
    const float* Wxr = (const float*)d_in[5];
    const float* bxr = (const float*)d_in[6];
    const float* Whr = (const float*)d_in[7];
    const float* bhr = (const float*)d_in[8];
    const float* Wfc = (const float*)d_in[9];
    const float* bfc = (const float*)d_in[10];
    float* out = (float*)d_out;

    cudaFuncSetAttribute(fused_scan,
        cudaFuncAttributeMaxDynamicSharedMemorySize, FSCAN_SMEM_BYTES);

    const size_t WH = 512 * 1024, WR = 512 * 512;

    init_kernel<<<64, 256>>>();

    // layer-1 input projections (slab 0)
    dim3 g1(8, 32), g2(4, 32);
    bulk_gemm<<<g1, 256>>>(x, Wxh, bxh, 1024, 0);
    bulk_gemm<<<g2, 256>>>(x, Wxr, bxr, 512, 1);

    // uniform dual-role fused scan (L1 slab 0, L2 slab 2)
    fused_scan<<<128, 1024, FSCAN_SMEM_BYTES>>>(
        Whh, bhh, Whr, bhr,
        Whh + 2 * WH, bhh + 2 * 1024, Whr + 2 * WR, bhr + 2 * 512,
        Wxh + 2 * WH, bxh + 2 * 1024, Wxr + 2 * WR, bxr + 2 * 512);

    // reverse branch: two single steps (slabs 1, 3)
    rev_step<<<32, 512>>>(x + 127 * 512, 128 * 512, 0,
        Wxh + 1 * WH, bxh + 1 * 1024, bhh + 1 * 1024,
        Wxr + 1 * WR, bxr + 1 * 512, bhr + 1 * 512, 0);
    rev_step<<<32, 512>>>(nullptr, 512, 1,
        Wxh + 3 * WH, bxh + 3 * 1024, bhh + 3 * 1024,
        Wxr + 3 * WR, bxr + 3 * 512, bhr + 3 * 512, 1);

    fc_kernel<<<32, 512>>>(Wfc, bfc, out);
}